// round 12
// baseline (speedup 1.0000x reference)
#include <cuda_runtime.h>
#include <cuda_fp16.h>
#include <math.h>
#include <stdint.h>

#define NT 4000
#define NS 5000
#define LOG2E 1.4426950408889634f
typedef unsigned short u16;

// ===================== scratch =============================================
__device__ __align__(16) u16 g_A0f[16000000];
__device__ __align__(16) u16 g_A1f[20000000];
__device__ __align__(16) u16 g_A2f[25000000];
__device__ __align__(16) u16 g_Es[25000000];
__device__ __align__(16) u16 g_Ev[20000000];
__device__ __align__(16) u16 g_Et[16000000];
__device__ __align__(16) u16 g_Xf[2432000];
__device__ float g_Mrow[5120];
__device__ float g_src_inv[NS];
__device__ float g_vna_inv[NT];
__device__ float g_tgt_inv[NT];
__device__ __align__(16) float g_lr[3 * NS * 128];
__device__ __align__(16) float g_semb[3 * NT * 128];
__device__ __align__(16) float g_Y[6200000];
__device__ __align__(16) float g_xt[NT * 128];

// ===================== PTX helpers =========================================
__device__ __forceinline__ uint32_t smem_u32(const void* p) {
    uint32_t a;
    asm("{ .reg .u64 t; cvta.to.shared.u64 t, %1; cvt.u32.u64 %0, t; }" : "=r"(a) : "l"(p));
    return a;
}
#define CP_ASYNC16(saddr, gaddr, sz) \
    asm volatile("cp.async.ca.shared.global [%0], [%1], 16, %2;" :: "r"(saddr), "l"(gaddr), "r"(sz))
#define CP_COMMIT() asm volatile("cp.async.commit_group;" ::: "memory")
#define CP_WAIT1()  asm volatile("cp.async.wait_group 1;" ::: "memory")
#define LDSM4(r, a) \
    asm volatile("ldmatrix.sync.aligned.m8n8.x4.shared.b16 {%0,%1,%2,%3}, [%4];" \
        : "=r"((r)[0]), "=r"((r)[1]), "=r"((r)[2]), "=r"((r)[3]) : "r"(a))
#define MMA_FP16(c, A, b0, b1) \
    asm volatile("mma.sync.aligned.m16n8k16.row.col.f32.f16.f16.f32 " \
        "{%0,%1,%2,%3},{%4,%5,%6,%7},{%8,%9},{%0,%1,%2,%3};" \
        : "+f"((c)[0]), "+f"((c)[1]), "+f"((c)[2]), "+f"((c)[3]) \
        : "r"((A)[0]), "r"((A)[1]), "r"((A)[2]), "r"((A)[3]), "r"(b0), "r"(b1))

__device__ __forceinline__ uint32_t pack_h2(float a, float b) {
    return (uint32_t)__half_as_ushort(__float2half_rn(a)) |
           ((uint32_t)__half_as_ushort(__float2half_rn(b)) << 16);
}
__device__ __forceinline__ uint4 pack8(const float* v) {
    uint4 H;
    H.x = pack_h2(v[0], v[1]); H.y = pack_h2(v[2], v[3]);
    H.z = pack_h2(v[4], v[5]); H.w = pack_h2(v[6], v[7]);
    return H;
}
__device__ __forceinline__ uint32_t swz(uint32_t x) { return x ^ ((x >> 3) & 0x70); }

// ===================== small kernels ========================================
__global__ void unpack_kernel(const float* __restrict__ xp, float* __restrict__ out, int n) {
    int i = blockIdx.x * blockDim.x + threadIdx.x;
    if (i >= n * 128) return;
    int r = i >> 7, c = i & 127, b = c >> 6, d = c & 63;
    out[((size_t)b * n + r) * 64 + d] = xp[i];
}
__global__ void tofp16_kernel(const float* __restrict__ A, u16* __restrict__ F, int n4) {
    int i = blockIdx.x * blockDim.x + threadIdx.x;
    if (i >= n4) return;
    float4 v = ((const float4*)A)[i];
    uint2 o;
    o.x = pack_h2(v.x * 4096.f, v.y * 4096.f);
    o.y = pack_h2(v.z * 4096.f, v.w * 4096.f);
    ((uint2*)F)[i] = o;
}
__global__ __launch_bounds__(256)
void pack_prep(const float* __restrict__ x, float* __restrict__ xp,
               u16* __restrict__ Xf, int n)
{
    __shared__ float t[8][128];
    const int tid = threadIdx.x, r0 = blockIdx.x * 8;
    for (int i = tid; i < 1024; i += 256) {
        int r = i >> 7, c = i & 127, b = c >> 6, d = c & 63;
        float v = x[((size_t)b * n + r0 + r) * 64 + d];
        xp[(size_t)(r0 + r) * 128 + c] = v;
        t[r][c] = v;
    }
    __syncthreads();
    if (tid < 128) {
        float v[8];
#pragma unroll
        for (int j = 0; j < 8; j++) v[j] = t[j][tid];
        *(uint4*)(Xf + (size_t)tid * n + r0) = pack8(v);
    }
}

// ===================== adaptive adjacency via tensor cores ==================
// CTA = 64 rows x ncols (128-col chunks). nv1 split hi/lo fp16 (3-pass MMA).
// MODE 0: track row max -> Mrow. MODE 1: E = exp2((d-max)*log2e) fp16 + 1/rowsum.
#define ADPSM 49152   // Ah 8K | Al 8K | Bh 16K | Bl 16K
template<int MODE>
__global__ __launch_bounds__(256, 2)
void adp_pass(const float* __restrict__ nv1, const float* __restrict__ nv2,
              float* __restrict__ Mrow_g, u16* __restrict__ E,
              float* __restrict__ inv, int nrows, int ncols)
{
    extern __shared__ __align__(128) char dsm[];
    __shared__ float redbuf[2][64];
    __shared__ float MrowS[64];
    const uint32_t sA = smem_u32(dsm), sAl = sA + 8192, sB = sA + 16384, sBl = sA + 32768;
    const int tid = threadIdx.x, lane = tid & 31, wid = tid >> 5;
    const int wm = wid >> 1, wn = wid & 1;
    const int r0 = blockIdx.x * 64;

    // load nv1 [64][30] -> hi/lo fp16, zero-pad k to 32
    for (int i = tid; i < 64 * 32; i += 256) {
        int r = i >> 5, q = i & 31;
        float v = (r0 + r < nrows && q < 30) ? nv1[(size_t)(r0 + r) * 30 + q] : 0.f;
        __half h = __float2half_rn(v);
        float l = v - __half2float(h);
        uint32_t off = swz((uint32_t)r * 128 + q * 2);
        *(u16*)(dsm + off) = __half_as_ushort(h);
        *(u16*)(dsm + 8192 + off) = __half_as_ushort(__float2half_rn(l));
    }
    if (MODE == 1 && tid < 64)
        MrowS[tid] = (r0 + tid < nrows) ? Mrow_g[r0 + tid] : 0.f;
    __syncthreads();

    uint32_t arow, axor;
    { int r = wm * 16 + (lane & 7) + (((lane >> 3) & 1) << 3);
      arow = (uint32_t)r * 128; axor = ((uint32_t)r * 16) & 0x70; }
    const uint32_t akbs = ((lane >> 4) & 1) * 16;
    uint32_t brow[4], bxor[4];
#pragma unroll
    for (int bt = 0; bt < 4; bt++) {
        int r = wn * 64 + bt * 16 + (lane & 7) + (((lane >> 4) & 1) << 3);
        brow[bt] = (uint32_t)r * 128; bxor[bt] = ((uint32_t)r * 16) & 0x70;
    }
    const uint32_t bkbs = ((lane >> 3) & 1) * 16;

    const int gr0 = r0 + wm * 16 + (lane >> 2), gr1 = gr0 + 8;
    float mx0 = 0.f, mx1 = 0.f, ps0 = 0.f, ps1 = 0.f;
    float M0 = 0.f, M1 = 0.f;
    if (MODE == 1) { M0 = MrowS[wm * 16 + (lane >> 2)]; M1 = MrowS[wm * 16 + (lane >> 2) + 8]; }

    const int nch = (ncols + 127) / 128;
    for (int ch = 0; ch < nch; ch++) {
        const int c0 = ch * 128;
        __syncthreads();
        for (int i = tid; i < 128 * 32; i += 256) {
            int q = i >> 7, j = i & 127;
            int c = c0 + j;
            float v = (c < ncols && q < 30) ? nv2[(size_t)q * ncols + c] : 0.f;
            __half h = __float2half_rn(v);
            float l = v - __half2float(h);
            uint32_t off = swz((uint32_t)j * 128 + q * 2);
            *(u16*)(dsm + 16384 + off) = __half_as_ushort(h);
            *(u16*)(dsm + 32768 + off) = __half_as_ushort(__float2half_rn(l));
        }
        __syncthreads();

        float acc[8][4];
#pragma unroll
        for (int j = 0; j < 8; j++)
#pragma unroll
            for (int q = 0; q < 4; q++) acc[j][q] = 0.f;
#pragma unroll
        for (int ks = 0; ks < 2; ks++) {
            const uint32_t kb = ks * 32;
            uint32_t fah[4], fal[4], fbh[4][4], fbl[4][4];
            LDSM4(fah, sA + arow + ((kb + akbs) ^ axor));
            LDSM4(fal, sAl + arow + ((kb + akbs) ^ axor));
#pragma unroll
            for (int bt = 0; bt < 4; bt++) {
                LDSM4(fbh[bt], sB + brow[bt] + ((kb + bkbs) ^ bxor[bt]));
                LDSM4(fbl[bt], sBl + brow[bt] + ((kb + bkbs) ^ bxor[bt]));
            }
#pragma unroll
            for (int nt = 0; nt < 8; nt++) {
                const int g = nt >> 1, h = (nt & 1) << 1;
                MMA_FP16(acc[nt], fah, fbh[g][h], fbh[g][h + 1]);
                MMA_FP16(acc[nt], fah, fbl[g][h], fbl[g][h + 1]);
                MMA_FP16(acc[nt], fal, fbh[g][h], fbh[g][h + 1]);
            }
        }

#pragma unroll
        for (int nt = 0; nt < 8; nt++) {
            int c = c0 + wn * 64 + nt * 8 + ((lane & 3) << 1);
            float d00 = fmaxf(acc[nt][0], 0.f), d01 = fmaxf(acc[nt][1], 0.f);
            float d10 = fmaxf(acc[nt][2], 0.f), d11 = fmaxf(acc[nt][3], 0.f);
            if (MODE == 0) {
                if (c < ncols) {
                    mx0 = fmaxf(mx0, fmaxf(d00, d01));
                    mx1 = fmaxf(mx1, fmaxf(d10, d11));
                }
            } else {
                __half2 h0 = __floats2half2_rn((d00 - M0) * LOG2E, (d01 - M0) * LOG2E);
                __half2 h1 = __floats2half2_rn((d10 - M1) * LOG2E, (d11 - M1) * LOG2E);
                uint32_t e0, e1;
                asm("ex2.approx.f16x2 %0, %1;" : "=r"(e0) : "r"(*(uint32_t*)&h0));
                asm("ex2.approx.f16x2 %0, %1;" : "=r"(e1) : "r"(*(uint32_t*)&h1));
                if (c < ncols) {
                    float2 f0 = __half22float2(*(__half2*)&e0);
                    float2 f1 = __half22float2(*(__half2*)&e1);
                    ps0 += f0.x + f0.y;
                    ps1 += f1.x + f1.y;
                    if (gr0 < nrows) *(uint32_t*)(E + (size_t)gr0 * ncols + c) = e0;
                    if (gr1 < nrows) *(uint32_t*)(E + (size_t)gr1 * ncols + c) = e1;
                }
            }
        }
    }

    // reduce across lane&3 (quad), stash per wn, combine
    float v0 = (MODE == 0) ? mx0 : ps0, v1 = (MODE == 0) ? mx1 : ps1;
#pragma unroll
    for (int off = 1; off <= 2; off <<= 1) {
        float o0 = __shfl_xor_sync(0xffffffffu, v0, off);
        float o1 = __shfl_xor_sync(0xffffffffu, v1, off);
        if (MODE == 0) { v0 = fmaxf(v0, o0); v1 = fmaxf(v1, o1); }
        else           { v0 += o0;           v1 += o1; }
    }
    if ((lane & 3) == 0) {
        redbuf[wn][wm * 16 + (lane >> 2)] = v0;
        redbuf[wn][wm * 16 + (lane >> 2) + 8] = v1;
    }
    __syncthreads();
    if (tid < 64 && r0 + tid < nrows) {
        float a = redbuf[0][tid], b = redbuf[1][tid];
        if (MODE == 0) Mrow_g[r0 + tid] = fmaxf(a, b);
        else           inv[r0 + tid] = 1.0f / (a + b);
    }
}

// ===================== merged-support split-K HMMA GEMM (R10 config) ========
#define GKT 64
#define STAGE_B 16384
#define SMEM_GEMM (2 * STAGE_B)

__device__ __forceinline__ void stage_ldm(uint32_t sdst,
    const u16* __restrict__ Ad, const u16* __restrict__ Ae, const u16* __restrict__ B,
    int row0, int kbase, int n, int kend, int m, int tid)
{
#pragma unroll
    for (int t = 0; t < 2; t++) {
        int id = tid + t * 128;
        int r = id >> 3, kc = id & 7;
        int gr = row0 + r, gk = kbase + kc * 8;
        bool v = (gr < n) && (gk < kend);
        size_t gi = (size_t)(v ? gr : 0) * m + (v ? gk : 0);
        uint32_t sw = swz(r * 128 + kc * 16);
        unsigned sz = v ? 16u : 0u;
        CP_ASYNC16(sdst + sw, Ad + gi, sz);
        CP_ASYNC16(sdst + 4096 + sw, Ae + gi, sz);
    }
#pragma unroll
    for (int t = 0; t < 4; t++) {
        int id = tid + t * 128;
        int cr = id >> 3, kc = id & 7;
        int gk = kbase + kc * 8;
        bool v = (gk < kend);
        size_t gi = (size_t)cr * m + (v ? gk : 0);
        uint32_t sw = swz(cr * 128 + kc * 16);
        CP_ASYNC16(sdst + 8192 + sw, B + gi, v ? 16u : 0u);
    }
}

__global__ __launch_bounds__(128, 4)
void hmma_gemm3m(const u16* __restrict__ Af, const u16* __restrict__ Ef,
                 const float* __restrict__ invsum,
                 const u16* __restrict__ Xf,
                 float* __restrict__ Y, int n, int m, int mh, int ny)
{
    extern __shared__ __align__(128) char smem[];
    const uint32_t sb = smem_u32(smem);
    const int tid = threadIdx.x, lane = tid & 31, wid = tid >> 5;
    const int wm = wid >> 1, wn = wid & 1;
    const int tile = blockIdx.x >> 1, nh = blockIdx.x & 1;
    const int row0 = tile * 32, col0 = nh * 64;
    const int yb = blockIdx.y % ny, zs = blockIdx.y / ny;
    const u16* __restrict__ B = Xf + ((size_t)yb * 128 + col0) * m;
    const int k0 = zs * mh, kend = min(m, k0 + mh);
    const int ktn = (kend - k0 + GKT - 1) / GKT;

    float accD[4][4], accE[4][4];
#pragma unroll
    for (int j = 0; j < 4; j++)
#pragma unroll
        for (int q = 0; q < 4; q++) { accD[j][q] = 0.f; accE[j][q] = 0.f; }

    uint32_t arow, axor;
    { int r = wm * 16 + (lane & 7) + (((lane >> 3) & 1) << 3);
      arow = (uint32_t)r * 128; axor = ((uint32_t)r * 16) & 0x70; }
    const uint32_t akbs = ((lane >> 4) & 1) * 16;
    uint32_t brow[2], bxor[2];
#pragma unroll
    for (int bt = 0; bt < 2; bt++) {
        int r = wn * 32 + bt * 16 + (lane & 7) + (((lane >> 4) & 1) << 3);
        brow[bt] = (uint32_t)r * 128; bxor[bt] = ((uint32_t)r * 16) & 0x70;
    }
    const uint32_t bkbs = ((lane >> 3) & 1) * 16;

    stage_ldm(sb, Af, Ef, B, row0, k0, n, kend, m, tid);
    CP_COMMIT();

    for (int kt = 0; kt < ktn; kt++) {
        if (kt + 1 < ktn)
            stage_ldm(sb + ((kt + 1) & 1) * STAGE_B, Af, Ef, B,
                      row0, k0 + (kt + 1) * GKT, n, kend, m, tid);
        CP_COMMIT();
        CP_WAIT1();
        __syncthreads();
        const uint32_t stb = sb + (kt & 1) * STAGE_B;
#pragma unroll
        for (int ks = 0; ks < 4; ks++) {
            const uint32_t kb = ks * 32;
            uint32_t fad[4], fae[4], fb[2][4];
            LDSM4(fad, stb + arow + ((kb + akbs) ^ axor));
            LDSM4(fae, stb + 4096 + arow + ((kb + akbs) ^ axor));
#pragma unroll
            for (int bt = 0; bt < 2; bt++)
                LDSM4(fb[bt], stb + 8192 + brow[bt] + ((kb + bkbs) ^ bxor[bt]));
#pragma unroll
            for (int nt = 0; nt < 4; nt++) {
                const int g = nt >> 1, h = (nt & 1) << 1;
                MMA_FP16(accD[nt], fad, fb[g][h], fb[g][h + 1]);
                MMA_FP16(accE[nt], fae, fb[g][h], fb[g][h + 1]);
            }
        }
        __syncthreads();
    }

    float* __restrict__ Yd = Y + (size_t)(zs * 2 * ny + yb * 2) * n * 128;
    float* __restrict__ Ye = Yd + (size_t)n * 128;
    const int gr0 = row0 + wm * 16 + (lane >> 2), gr1 = gr0 + 8;
    const float SD = 2.44140625e-4f;
    const float e0 = (gr0 < n) ? invsum[gr0] : 0.f;
    const float e1 = (gr1 < n) ? invsum[gr1] : 0.f;
#pragma unroll
    for (int nt = 0; nt < 4; nt++) {
        int col = col0 + wn * 32 + nt * 8 + ((lane & 3) << 1);
        if (gr0 < n) {
            *(float2*)(Yd + (size_t)gr0 * 128 + col) =
                make_float2(accD[nt][0] * SD, accD[nt][1] * SD);
            *(float2*)(Ye + (size_t)gr0 * 128 + col) =
                make_float2(accE[nt][0] * e0, accE[nt][1] * e0);
        }
        if (gr1 < n) {
            *(float2*)(Yd + (size_t)gr1 * 128 + col) =
                make_float2(accD[nt][2] * SD, accD[nt][3] * SD);
            *(float2*)(Ye + (size_t)gr1 * 128 + col) =
                make_float2(accE[nt][2] * e1, accE[nt][3] * e1);
        }
    }
}

// ===================== source epilogue ======================================
__global__ __launch_bounds__(256)
void epi_src(const float* __restrict__ Y, const float* __restrict__ W,
             const float* __restrict__ bias, const float* __restrict__ prev,
             float* __restrict__ out, u16* __restrict__ Xf, int n, size_t ps)
{
    __shared__ float Ws[128][64];
    __shared__ float Y1s[8][128];
    __shared__ float Y2s[8][128];
    __shared__ float oS[8][128];
    const int tid = threadIdx.x, r0 = blockIdx.x * 8;
    for (int i = tid; i < 8192; i += 256) Ws[i >> 6][i & 63] = W[i];
    const float* __restrict__ Y2 = Y + (size_t)n * 128;
    for (int i = tid; i < 1024; i += 256) {
        int r = i >> 7, c = i & 127;
        size_t gi = (size_t)(r0 + r) * 128 + c;
        Y1s[r][c] = Y[gi] + Y[gi + ps];
        Y2s[r][c] = Y2[gi] + Y2[gi + ps];
    }
    __syncthreads();
    const int c = tid & 127, rg = tid >> 7, d = c & 63, b64 = c & 64;
    const float bv = bias[d];
    for (int rr = rg; rr < 8; rr += 2) {
        float acc = bv;
#pragma unroll
        for (int k = 0; k < 64; k++) {
            acc = fmaf(Y1s[rr][b64 + k], Ws[k][d], acc);
            acc = fmaf(Y2s[rr][b64 + k], Ws[64 + k][d], acc);
        }
        float g = prev[(size_t)(r0 + rr) * 128 + c] + fmaxf(acc, 0.f);
        out[(size_t)(r0 + rr) * 128 + c] = g;
        oS[rr][c] = g;
    }
    __syncthreads();
    if (tid < 128) {
        float v[8];
#pragma unroll
        for (int j = 0; j < 8; j++) v[j] = oS[j][tid];
        *(uint4*)(Xf + (size_t)tid * n + r0) = pack8(v);
    }
}

// ===================== VNA epilogue =========================================
__global__ __launch_bounds__(256)
void epi_vna(const float* __restrict__ Y, const float* __restrict__ W,
             const float* __restrict__ bias, float* __restrict__ semb, int n, size_t ps)
{
    __shared__ float Ws[128][64];
    __shared__ float Y1s[8][128];
    __shared__ float Y2s[8][128];
    const int tid = threadIdx.x, r0 = blockIdx.x * 8, y = blockIdx.y;
    const float* __restrict__ Wp = W + y * 8192;
    const float* __restrict__ Y1 = Y + (size_t)(2 * y) * n * 128;
    const float* __restrict__ Y2 = Y1 + (size_t)n * 128;
    float* __restrict__ out = semb + (size_t)y * n * 128;
    for (int i = tid; i < 8192; i += 256) Ws[i >> 6][i & 63] = Wp[i];
    for (int i = tid; i < 1024; i += 256) {
        int r = i >> 7, c = i & 127;
        size_t gi = (size_t)(r0 + r) * 128 + c;
        Y1s[r][c] = Y1[gi] + Y1[gi + ps];
        Y2s[r][c] = Y2[gi] + Y2[gi + ps];
    }
    __syncthreads();
    const int c = tid & 127, rg = tid >> 7, d = c & 63, b64 = c & 64;
    const float bv = bias[y * 64 + d];
    for (int rr = rg; rr < 8; rr += 2) {
        float acc = bv;
#pragma unroll
        for (int k = 0; k < 64; k++) {
            acc = fmaf(Y1s[rr][b64 + k], Ws[k][d], acc);
            acc = fmaf(Y2s[rr][b64 + k], Ws[64 + k][d], acc);
        }
        out[(size_t)(r0 + rr) * 128 + c] = fmaxf(acc, 0.f);
    }
}

// ===================== target epilogue + gated fusion =======================
#define SMEM_TGT 49152
__global__ __launch_bounds__(256)
void epi_tgt(const float* __restrict__ Y, const float* __restrict__ W,
             const float* __restrict__ bias, const float* __restrict__ S,
             const float* __restrict__ fWt, const float* __restrict__ fWs,
             const float* __restrict__ fb, float* __restrict__ xt,
             u16* __restrict__ Xf, int n, size_t ps)
{
    extern __shared__ __align__(16) char dsm[];
    float* Wbuf = (float*)dsm;
    float (*Y1s)[128] = (float(*)[128])(dsm + 32768);
    float (*Y2s)[128] = (float(*)[128])(dsm + 36864);
    float (*tS)[128]  = (float(*)[128])(dsm + 40960);
    float (*sS)[128]  = (float(*)[128])(dsm + 45056);
    const int tid = threadIdx.x, r0 = blockIdx.x * 8;
    for (int i = tid; i < 8192; i += 256) Wbuf[i] = W[i];
    const float* __restrict__ Y2 = Y + (size_t)n * 128;
    for (int i = tid; i < 1024; i += 256) {
        int r = i >> 7, c = i & 127;
        size_t gi = (size_t)(r0 + r) * 128 + c;
        Y1s[r][c] = Y[gi] + Y[gi + ps];
        Y2s[r][c] = Y2[gi] + Y2[gi + ps];
        sS[r][c] = S[gi];
    }
    __syncthreads();
    const int c = tid & 127, rg = tid >> 7, d = c & 63, b64 = c & 64;
    const float bv = bias[d];
    for (int rr = rg; rr < 8; rr += 2) {
        float acc = bv;
#pragma unroll
        for (int k = 0; k < 64; k++) {
            acc = fmaf(Y1s[rr][b64 + k], Wbuf[k * 64 + d], acc);
            acc = fmaf(Y2s[rr][b64 + k], Wbuf[(64 + k) * 64 + d], acc);
        }
        tS[rr][c] = fmaxf(acc, 0.f);
    }
    __syncthreads();
    for (int i = tid; i < 4096; i += 256) { Wbuf[i] = fWt[i]; Wbuf[4096 + i] = fWs[i]; }
    __syncthreads();
    const float fbv = fb[d];
    for (int rr = rg; rr < 8; rr += 2) {
        float za = fbv;
#pragma unroll
        for (int k = 0; k < 64; k++) {
            za = fmaf(tS[rr][b64 + k], Wbuf[k * 64 + d], za);
            za = fmaf(sS[rr][b64 + k], Wbuf[4096 + k * 64 + d], za);
        }
        float z = 1.f / (1.f + expf(-za));
        float tv = tS[rr][c], sv = sS[rr][c];
        size_t gi = (size_t)(r0 + rr) * 128 + c;
        float nx = xt[gi] + z * tv + (1.f - z) * sv;
        xt[gi] = nx;
        Y1s[rr][c] = nx;
    }
    __syncthreads();
    if (Xf && tid < 128) {
        float v[8];
#pragma unroll
        for (int j = 0; j < 8; j++) v[j] = Y1s[j][tid];
        *(uint4*)(Xf + (size_t)tid * n + r0) = pack8(v);
    }
}

// ===================== launcher =============================================
extern "C" void kernel_launch(void* const* d_in, const int* in_sizes, int n_in,
                              void* d_out, int out_size)
{
    (void)in_sizes; (void)n_in; (void)out_size;
    const float* A0      = (const float*)d_in[0];
    const float* A1      = (const float*)d_in[1];
    const float* A2      = (const float*)d_in[2];
    const float* x0      = (const float*)d_in[3];
    const float* x1      = (const float*)d_in[4];
    const float* src_nv1 = (const float*)d_in[5];
    const float* src_nv2 = (const float*)d_in[6];
    const float* src_W   = (const float*)d_in[7];
    const float* src_b   = (const float*)d_in[8];
    const float* vna_nv1 = (const float*)d_in[9];
    const float* vna_nv2 = (const float*)d_in[10];
    const float* vna_W   = (const float*)d_in[11];
    const float* vna_b   = (const float*)d_in[12];
    const float* tgt_nv1 = (const float*)d_in[13];
    const float* tgt_nv2 = (const float*)d_in[14];
    const float* tgt_W   = (const float*)d_in[15];
    const float* tgt_b   = (const float*)d_in[16];
    const float* fus_Wt  = (const float*)d_in[17];
    const float* fus_Ws  = (const float*)d_in[18];
    const float* fus_b   = (const float*)d_in[19];

    u16 *A0f, *A1f, *A2f, *Es, *Ev, *Et, *Xf;
    float *Mrow, *src_inv, *vna_inv, *tgt_inv, *lr, *semb, *Yb, *xtb;
    cudaGetSymbolAddress((void**)&A0f, g_A0f);
    cudaGetSymbolAddress((void**)&A1f, g_A1f);
    cudaGetSymbolAddress((void**)&A2f, g_A2f);
    cudaGetSymbolAddress((void**)&Es, g_Es);
    cudaGetSymbolAddress((void**)&Ev, g_Ev);
    cudaGetSymbolAddress((void**)&Et, g_Et);
    cudaGetSymbolAddress((void**)&Xf, g_Xf);
    cudaGetSymbolAddress((void**)&Mrow, g_Mrow);
    cudaGetSymbolAddress((void**)&src_inv, g_src_inv);
    cudaGetSymbolAddress((void**)&vna_inv, g_vna_inv);
    cudaGetSymbolAddress((void**)&tgt_inv, g_tgt_inv);
    cudaGetSymbolAddress((void**)&lr, g_lr);
    cudaGetSymbolAddress((void**)&semb, g_semb);
    cudaGetSymbolAddress((void**)&Yb, g_Y);
    cudaGetSymbolAddress((void**)&xtb, g_xt);

    cudaFuncSetAttribute(hmma_gemm3m, cudaFuncAttributeMaxDynamicSharedMemorySize, SMEM_GEMM);
    cudaFuncSetAttribute(epi_tgt, cudaFuncAttributeMaxDynamicSharedMemorySize, SMEM_TGT);
    cudaFuncSetAttribute(adp_pass<0>, cudaFuncAttributeMaxDynamicSharedMemorySize, ADPSM);
    cudaFuncSetAttribute(adp_pass<1>, cudaFuncAttributeMaxDynamicSharedMemorySize, ADPSM);

    const size_t SLOT = (size_t)128 * NS;
    u16* Xf3 = Xf + 3 * SLOT;
    const int xS = ((NS + 31) / 32) * 2;   // 314
    const int xT = ((NT + 31) / 32) * 2;   // 250
    const int mhS = 2560, mhT = 2048;
    const size_t psS = (size_t)2 * NS * 128;
    const size_t psT1 = (size_t)2 * NT * 128;
    const size_t psT3 = (size_t)6 * NT * 128;
    const int gS = (NS + 63) / 64, gT = (NT + 63) / 64;   // 79, 63

    // ---- src chain first (profiled launch idx 3 = adp or GEMM) ----
    pack_prep<<<NS / 8, 256>>>(x1, lr, Xf, NS);
    tofp16_kernel<<<(NS * NS / 4 + 255) / 256, 256>>>(A2, A2f, NS * NS / 4);
    adp_pass<0><<<gS, 256, ADPSM>>>(src_nv1, src_nv2, Mrow, (u16*)nullptr, (float*)nullptr, NS, NS);
    adp_pass<1><<<gS, 256, ADPSM>>>(src_nv1, src_nv2, Mrow, Es, src_inv, NS, NS);
    for (int i = 0; i < 2; i++) {
        hmma_gemm3m<<<dim3(xS, 2), 128, SMEM_GEMM>>>(A2f, Es, src_inv,
            Xf + i * SLOT, Yb, NS, NS, mhS, 1);
        epi_src<<<NS / 8, 256>>>(Yb, src_W + i * 8192, src_b + i * 64,
            lr + (size_t)i * NS * 128, lr + (size_t)(i + 1) * NS * 128,
            Xf + (i + 1) * SLOT, NS, psS);
    }

    // ---- rest of prep ----
    pack_prep<<<NT / 8, 256>>>(x0, xtb, Xf3, NT);
    tofp16_kernel<<<(NT * NT / 4 + 255) / 256, 256>>>(A0, A0f, NT * NT / 4);
    tofp16_kernel<<<(NT * NS / 4 + 255) / 256, 256>>>(A1, A1f, NT * NS / 4);
    adp_pass<0><<<gT, 256, ADPSM>>>(vna_nv1, vna_nv2, Mrow, (u16*)nullptr, (float*)nullptr, NT, NS);
    adp_pass<1><<<gT, 256, ADPSM>>>(vna_nv1, vna_nv2, Mrow, Ev, vna_inv, NT, NS);
    adp_pass<0><<<gT, 256, ADPSM>>>(tgt_nv1, tgt_nv2, Mrow, (u16*)nullptr, (float*)nullptr, NT, NT);
    adp_pass<1><<<gT, 256, ADPSM>>>(tgt_nv1, tgt_nv2, Mrow, Et, tgt_inv, NT, NT);

    // ---- VNA block: 3 layers batched, K-split 2 ----
    hmma_gemm3m<<<dim3(xT, 6), 128, SMEM_GEMM>>>(A1f, Ev, vna_inv, Xf, Yb, NT, NS, mhS, 3);
    epi_vna<<<dim3(NT / 8, 3), 256>>>(Yb, vna_W, vna_b, semb, NT, psT3);

    // ---- Target GC block with gated fusion ----
    for (int i = 0; i < 3; i++) {
        hmma_gemm3m<<<dim3(xT, 2), 128, SMEM_GEMM>>>(A0f, Et, tgt_inv, Xf3, Yb, NT, NT, mhT, 1);
        epi_tgt<<<NT / 8, 256, SMEM_TGT>>>(Yb, tgt_W + i * 8192, tgt_b + i * 64,
            semb + (size_t)i * NT * 128, fus_Wt + i * 4096, fus_Ws + i * 4096,
            fus_b + i * 64, xtb, (i < 2) ? Xf3 : (u16*)nullptr, NT, psT1);
    }

    unpack_kernel<<<(NT * 128 + 255) / 256, 256>>>(xtb, (float*)d_out, NT);
}

// round 13
// speedup vs baseline: 1.3737x; 1.3737x over previous
#include <cuda_runtime.h>
#include <cuda_fp16.h>
#include <math.h>
#include <stdint.h>

#define NT 4000
#define NS 5000
#define LOG2E 1.4426950408889634f
typedef unsigned short u16;

// ===================== scratch =============================================
__device__ __align__(16) u16 g_A0f[16000000];
__device__ __align__(16) u16 g_A1f[20000000];
__device__ __align__(16) u16 g_A2f[25000000];
__device__ __align__(16) u16 g_Es[25000000];
__device__ __align__(16) u16 g_Ev[20000000];
__device__ __align__(16) u16 g_Et[16000000];
__device__ __align__(16) u16 g_Xf[2432000];
__device__ unsigned g_Mrow[5120];
__device__ float g_psum[40960];
__device__ float g_src_inv[NS];
__device__ float g_vna_inv[NT];
__device__ float g_tgt_inv[NT];
__device__ __align__(16) float g_lr[3 * NS * 128];
__device__ __align__(16) float g_semb[3 * NT * 128];
__device__ __align__(16) float g_Y[6200000];
__device__ __align__(16) float g_xt[NT * 128];

// ===================== PTX helpers =========================================
__device__ __forceinline__ uint32_t smem_u32(const void* p) {
    uint32_t a;
    asm("{ .reg .u64 t; cvta.to.shared.u64 t, %1; cvt.u32.u64 %0, t; }" : "=r"(a) : "l"(p));
    return a;
}
#define CP_ASYNC16(saddr, gaddr, sz) \
    asm volatile("cp.async.ca.shared.global [%0], [%1], 16, %2;" :: "r"(saddr), "l"(gaddr), "r"(sz))
#define CP_COMMIT() asm volatile("cp.async.commit_group;" ::: "memory")
#define CP_WAIT1()  asm volatile("cp.async.wait_group 1;" ::: "memory")
#define LDSM4(r, a) \
    asm volatile("ldmatrix.sync.aligned.m8n8.x4.shared.b16 {%0,%1,%2,%3}, [%4];" \
        : "=r"((r)[0]), "=r"((r)[1]), "=r"((r)[2]), "=r"((r)[3]) : "r"(a))
#define MMA_FP16(c, A, b0, b1) \
    asm volatile("mma.sync.aligned.m16n8k16.row.col.f32.f16.f16.f32 " \
        "{%0,%1,%2,%3},{%4,%5,%6,%7},{%8,%9},{%0,%1,%2,%3};" \
        : "+f"((c)[0]), "+f"((c)[1]), "+f"((c)[2]), "+f"((c)[3]) \
        : "r"((A)[0]), "r"((A)[1]), "r"((A)[2]), "r"((A)[3]), "r"(b0), "r"(b1))

__device__ __forceinline__ uint32_t pack_h2(float a, float b) {
    return (uint32_t)__half_as_ushort(__float2half_rn(a)) |
           ((uint32_t)__half_as_ushort(__float2half_rn(b)) << 16);
}
__device__ __forceinline__ uint4 pack8(const float* v) {
    uint4 H;
    H.x = pack_h2(v[0], v[1]); H.y = pack_h2(v[2], v[3]);
    H.z = pack_h2(v[4], v[5]); H.w = pack_h2(v[6], v[7]);
    return H;
}
__device__ __forceinline__ uint32_t swz(uint32_t x) { return x ^ ((x >> 3) & 0x70); }

// ===================== small kernels ========================================
__global__ void zero_u(unsigned* p, int n) {
    int i = blockIdx.x * blockDim.x + threadIdx.x;
    if (i < n) p[i] = 0u;
}
__global__ void unpack_kernel(const float* __restrict__ xp, float* __restrict__ out, int n) {
    int i = blockIdx.x * blockDim.x + threadIdx.x;
    if (i >= n * 128) return;
    int r = i >> 7, c = i & 127, b = c >> 6, d = c & 63;
    out[((size_t)b * n + r) * 64 + d] = xp[i];
}
__global__ void tofp16_kernel(const float* __restrict__ A, u16* __restrict__ F, int n4) {
    int i = blockIdx.x * blockDim.x + threadIdx.x;
    if (i >= n4) return;
    float4 v = ((const float4*)A)[i];
    uint2 o;
    o.x = pack_h2(v.x * 4096.f, v.y * 4096.f);
    o.y = pack_h2(v.z * 4096.f, v.w * 4096.f);
    ((uint2*)F)[i] = o;
}
__global__ __launch_bounds__(256)
void pack_prep(const float* __restrict__ x, float* __restrict__ xp,
               u16* __restrict__ Xf, int n)
{
    __shared__ float t[8][128];
    const int tid = threadIdx.x, r0 = blockIdx.x * 8;
    for (int i = tid; i < 1024; i += 256) {
        int r = i >> 7, c = i & 127, b = c >> 6, d = c & 63;
        float v = x[((size_t)b * n + r0 + r) * 64 + d];
        xp[(size_t)(r0 + r) * 128 + c] = v;
        t[r][c] = v;
    }
    __syncthreads();
    if (tid < 128) {
        float v[8];
#pragma unroll
        for (int j = 0; j < 8; j++) v[j] = t[j][tid];
        *(uint4*)(Xf + (size_t)tid * n + r0) = pack8(v);
    }
}

// ===================== adaptive adjacency via tensor cores ==================
// grid (rowtiles, CS): CTA = 64 rows x (ncols/CS) column slice.
// MODE 0: atomicMax row maxima. MODE 1: E = exp2((d-max)*log2e) fp16 + psum slot.
#define ADPCS 8
#define ADPSM 49152
template<int MODE>
__global__ __launch_bounds__(256, 2)
void adp_pass(const float* __restrict__ nv1, const float* __restrict__ nv2,
              unsigned* __restrict__ Mrow_g, u16* __restrict__ E,
              float* __restrict__ psum, int nrows, int ncols)
{
    extern __shared__ __align__(128) char dsm[];
    __shared__ float redbuf[2][64];
    __shared__ float MrowS[64];
    const uint32_t sA = smem_u32(dsm), sAl = sA + 8192, sB = sA + 16384, sBl = sA + 32768;
    const int tid = threadIdx.x, lane = tid & 31, wid = tid >> 5;
    const int wm = wid >> 1, wn = wid & 1;
    const int r0 = blockIdx.x * 64, cy = blockIdx.y;

    for (int i = tid; i < 64 * 32; i += 256) {
        int r = i >> 5, q = i & 31;
        float v = (r0 + r < nrows && q < 30) ? nv1[(size_t)(r0 + r) * 30 + q] : 0.f;
        __half h = __float2half_rn(v);
        float l = v - __half2float(h);
        uint32_t off = swz((uint32_t)r * 128 + q * 2);
        *(u16*)(dsm + off) = __half_as_ushort(h);
        *(u16*)(dsm + 8192 + off) = __half_as_ushort(__float2half_rn(l));
    }
    if (MODE == 1 && tid < 64)
        MrowS[tid] = (r0 + tid < nrows) ? __uint_as_float(Mrow_g[r0 + tid]) : 0.f;
    __syncthreads();

    uint32_t arow, axor;
    { int r = wm * 16 + (lane & 7) + (((lane >> 3) & 1) << 3);
      arow = (uint32_t)r * 128; axor = ((uint32_t)r * 16) & 0x70; }
    const uint32_t akbs = ((lane >> 4) & 1) * 16;
    uint32_t brow[4], bxor[4];
#pragma unroll
    for (int bt = 0; bt < 4; bt++) {
        int r = wn * 64 + bt * 16 + (lane & 7) + (((lane >> 4) & 1) << 3);
        brow[bt] = (uint32_t)r * 128; bxor[bt] = ((uint32_t)r * 16) & 0x70;
    }
    const uint32_t bkbs = ((lane >> 3) & 1) * 16;

    const int gr0 = r0 + wm * 16 + (lane >> 2), gr1 = gr0 + 8;
    float mx0 = 0.f, mx1 = 0.f, ps0 = 0.f, ps1 = 0.f;
    float M0 = 0.f, M1 = 0.f;
    if (MODE == 1) { M0 = MrowS[wm * 16 + (lane >> 2)]; M1 = MrowS[wm * 16 + (lane >> 2) + 8]; }

    const int nch = (ncols + 127) / 128;
    const int cper = (nch + ADPCS - 1) / ADPCS;
    const int chLo = cy * cper, chHi = min(nch, chLo + cper);
    for (int ch = chLo; ch < chHi; ch++) {
        const int c0 = ch * 128;
        __syncthreads();
        for (int i = tid; i < 128 * 32; i += 256) {
            int q = i >> 7, j = i & 127;
            int c = c0 + j;
            float v = (c < ncols && q < 30) ? nv2[(size_t)q * ncols + c] : 0.f;
            __half h = __float2half_rn(v);
            float l = v - __half2float(h);
            uint32_t off = swz((uint32_t)j * 128 + q * 2);
            *(u16*)(dsm + 16384 + off) = __half_as_ushort(h);
            *(u16*)(dsm + 32768 + off) = __half_as_ushort(__float2half_rn(l));
        }
        __syncthreads();

        float acc[8][4];
#pragma unroll
        for (int j = 0; j < 8; j++)
#pragma unroll
            for (int q = 0; q < 4; q++) acc[j][q] = 0.f;
#pragma unroll
        for (int ks = 0; ks < 2; ks++) {
            const uint32_t kb = ks * 32;
            uint32_t fah[4], fal[4], fbh[4][4], fbl[4][4];
            LDSM4(fah, sA + arow + ((kb + akbs) ^ axor));
            LDSM4(fal, sAl + arow + ((kb + akbs) ^ axor));
#pragma unroll
            for (int bt = 0; bt < 4; bt++) {
                LDSM4(fbh[bt], sB + brow[bt] + ((kb + bkbs) ^ bxor[bt]));
                LDSM4(fbl[bt], sBl + brow[bt] + ((kb + bkbs) ^ bxor[bt]));
            }
#pragma unroll
            for (int nt = 0; nt < 8; nt++) {
                const int g = nt >> 1, h = (nt & 1) << 1;
                MMA_FP16(acc[nt], fah, fbh[g][h], fbh[g][h + 1]);
                MMA_FP16(acc[nt], fah, fbl[g][h], fbl[g][h + 1]);
                MMA_FP16(acc[nt], fal, fbh[g][h], fbh[g][h + 1]);
            }
        }

#pragma unroll
        for (int nt = 0; nt < 8; nt++) {
            int c = c0 + wn * 64 + nt * 8 + ((lane & 3) << 1);
            float d00 = fmaxf(acc[nt][0], 0.f), d01 = fmaxf(acc[nt][1], 0.f);
            float d10 = fmaxf(acc[nt][2], 0.f), d11 = fmaxf(acc[nt][3], 0.f);
            if (MODE == 0) {
                if (c < ncols) {
                    mx0 = fmaxf(mx0, fmaxf(d00, d01));
                    mx1 = fmaxf(mx1, fmaxf(d10, d11));
                }
            } else {
                __half2 h0 = __floats2half2_rn((d00 - M0) * LOG2E, (d01 - M0) * LOG2E);
                __half2 h1 = __floats2half2_rn((d10 - M1) * LOG2E, (d11 - M1) * LOG2E);
                uint32_t e0, e1;
                asm("ex2.approx.f16x2 %0, %1;" : "=r"(e0) : "r"(*(uint32_t*)&h0));
                asm("ex2.approx.f16x2 %0, %1;" : "=r"(e1) : "r"(*(uint32_t*)&h1));
                if (c < ncols) {
                    float2 f0 = __half22float2(*(__half2*)&e0);
                    float2 f1 = __half22float2(*(__half2*)&e1);
                    ps0 += f0.x + f0.y;
                    ps1 += f1.x + f1.y;
                    if (gr0 < nrows) *(uint32_t*)(E + (size_t)gr0 * ncols + c) = e0;
                    if (gr1 < nrows) *(uint32_t*)(E + (size_t)gr1 * ncols + c) = e1;
                }
            }
        }
    }

    float v0 = (MODE == 0) ? mx0 : ps0, v1 = (MODE == 0) ? mx1 : ps1;
#pragma unroll
    for (int off = 1; off <= 2; off <<= 1) {
        float o0 = __shfl_xor_sync(0xffffffffu, v0, off);
        float o1 = __shfl_xor_sync(0xffffffffu, v1, off);
        if (MODE == 0) { v0 = fmaxf(v0, o0); v1 = fmaxf(v1, o1); }
        else           { v0 += o0;           v1 += o1; }
    }
    if ((lane & 3) == 0) {
        redbuf[wn][wm * 16 + (lane >> 2)] = v0;
        redbuf[wn][wm * 16 + (lane >> 2) + 8] = v1;
    }
    __syncthreads();
    if (tid < 64 && r0 + tid < nrows) {
        float a = redbuf[0][tid], b = redbuf[1][tid];
        if (MODE == 0)
            atomicMax(Mrow_g + r0 + tid, __float_as_uint(fmaxf(a, b)));  // >=0: bit order == float order
        else
            psum[(size_t)(r0 + tid) * ADPCS + cy] = a + b;
    }
}

__global__ void adp_inv(const float* __restrict__ psum, float* __restrict__ inv, int nrows) {
    int r = blockIdx.x * blockDim.x + threadIdx.x;
    if (r >= nrows) return;
    float s = 0.f;
#pragma unroll
    for (int q = 0; q < ADPCS; q++) s += psum[(size_t)r * ADPCS + q];
    inv[r] = 1.0f / s;
}

// ===================== merged-support split-K HMMA GEMM (R10 config) ========
#define GKT 64
#define STAGE_B 16384
#define SMEM_GEMM (2 * STAGE_B)

__device__ __forceinline__ void stage_ldm(uint32_t sdst,
    const u16* __restrict__ Ad, const u16* __restrict__ Ae, const u16* __restrict__ B,
    int row0, int kbase, int n, int kend, int m, int tid)
{
#pragma unroll
    for (int t = 0; t < 2; t++) {
        int id = tid + t * 128;
        int r = id >> 3, kc = id & 7;
        int gr = row0 + r, gk = kbase + kc * 8;
        bool v = (gr < n) && (gk < kend);
        size_t gi = (size_t)(v ? gr : 0) * m + (v ? gk : 0);
        uint32_t sw = swz(r * 128 + kc * 16);
        unsigned sz = v ? 16u : 0u;
        CP_ASYNC16(sdst + sw, Ad + gi, sz);
        CP_ASYNC16(sdst + 4096 + sw, Ae + gi, sz);
    }
#pragma unroll
    for (int t = 0; t < 4; t++) {
        int id = tid + t * 128;
        int cr = id >> 3, kc = id & 7;
        int gk = kbase + kc * 8;
        bool v = (gk < kend);
        size_t gi = (size_t)cr * m + (v ? gk : 0);
        uint32_t sw = swz(cr * 128 + kc * 16);
        CP_ASYNC16(sdst + 8192 + sw, B + gi, v ? 16u : 0u);
    }
}

__global__ __launch_bounds__(128, 4)
void hmma_gemm3m(const u16* __restrict__ Af, const u16* __restrict__ Ef,
                 const float* __restrict__ invsum,
                 const u16* __restrict__ Xf,
                 float* __restrict__ Y, int n, int m, int mh, int ny)
{
    extern __shared__ __align__(128) char smem[];
    const uint32_t sb = smem_u32(smem);
    const int tid = threadIdx.x, lane = tid & 31, wid = tid >> 5;
    const int wm = wid >> 1, wn = wid & 1;
    const int tile = blockIdx.x >> 1, nh = blockIdx.x & 1;
    const int row0 = tile * 32, col0 = nh * 64;
    const int yb = blockIdx.y % ny, zs = blockIdx.y / ny;
    const u16* __restrict__ B = Xf + ((size_t)yb * 128 + col0) * m;
    const int k0 = zs * mh, kend = min(m, k0 + mh);
    const int ktn = (kend - k0 + GKT - 1) / GKT;

    float accD[4][4], accE[4][4];
#pragma unroll
    for (int j = 0; j < 4; j++)
#pragma unroll
        for (int q = 0; q < 4; q++) { accD[j][q] = 0.f; accE[j][q] = 0.f; }

    uint32_t arow, axor;
    { int r = wm * 16 + (lane & 7) + (((lane >> 3) & 1) << 3);
      arow = (uint32_t)r * 128; axor = ((uint32_t)r * 16) & 0x70; }
    const uint32_t akbs = ((lane >> 4) & 1) * 16;
    uint32_t brow[2], bxor[2];
#pragma unroll
    for (int bt = 0; bt < 2; bt++) {
        int r = wn * 32 + bt * 16 + (lane & 7) + (((lane >> 4) & 1) << 3);
        brow[bt] = (uint32_t)r * 128; bxor[bt] = ((uint32_t)r * 16) & 0x70;
    }
    const uint32_t bkbs = ((lane >> 3) & 1) * 16;

    stage_ldm(sb, Af, Ef, B, row0, k0, n, kend, m, tid);
    CP_COMMIT();

    for (int kt = 0; kt < ktn; kt++) {
        if (kt + 1 < ktn)
            stage_ldm(sb + ((kt + 1) & 1) * STAGE_B, Af, Ef, B,
                      row0, k0 + (kt + 1) * GKT, n, kend, m, tid);
        CP_COMMIT();
        CP_WAIT1();
        __syncthreads();
        const uint32_t stb = sb + (kt & 1) * STAGE_B;
#pragma unroll
        for (int ks = 0; ks < 4; ks++) {
            const uint32_t kb = ks * 32;
            uint32_t fad[4], fae[4], fb[2][4];
            LDSM4(fad, stb + arow + ((kb + akbs) ^ axor));
            LDSM4(fae, stb + 4096 + arow + ((kb + akbs) ^ axor));
#pragma unroll
            for (int bt = 0; bt < 2; bt++)
                LDSM4(fb[bt], stb + 8192 + brow[bt] + ((kb + bkbs) ^ bxor[bt]));
#pragma unroll
            for (int nt = 0; nt < 4; nt++) {
                const int g = nt >> 1, h = (nt & 1) << 1;
                MMA_FP16(accD[nt], fad, fb[g][h], fb[g][h + 1]);
                MMA_FP16(accE[nt], fae, fb[g][h], fb[g][h + 1]);
            }
        }
        __syncthreads();
    }

    float* __restrict__ Yd = Y + (size_t)(zs * 2 * ny + yb * 2) * n * 128;
    float* __restrict__ Ye = Yd + (size_t)n * 128;
    const int gr0 = row0 + wm * 16 + (lane >> 2), gr1 = gr0 + 8;
    const float SD = 2.44140625e-4f;
    const float e0 = (gr0 < n) ? invsum[gr0] : 0.f;
    const float e1 = (gr1 < n) ? invsum[gr1] : 0.f;
#pragma unroll
    for (int nt = 0; nt < 4; nt++) {
        int col = col0 + wn * 32 + nt * 8 + ((lane & 3) << 1);
        if (gr0 < n) {
            *(float2*)(Yd + (size_t)gr0 * 128 + col) =
                make_float2(accD[nt][0] * SD, accD[nt][1] * SD);
            *(float2*)(Ye + (size_t)gr0 * 128 + col) =
                make_float2(accE[nt][0] * e0, accE[nt][1] * e0);
        }
        if (gr1 < n) {
            *(float2*)(Yd + (size_t)gr1 * 128 + col) =
                make_float2(accD[nt][2] * SD, accD[nt][3] * SD);
            *(float2*)(Ye + (size_t)gr1 * 128 + col) =
                make_float2(accE[nt][2] * e1, accE[nt][3] * e1);
        }
    }
}

// ===================== source epilogue ======================================
__global__ __launch_bounds__(256)
void epi_src(const float* __restrict__ Y, const float* __restrict__ W,
             const float* __restrict__ bias, const float* __restrict__ prev,
             float* __restrict__ out, u16* __restrict__ Xf, int n, size_t ps)
{
    __shared__ float Ws[128][64];
    __shared__ float Y1s[8][128];
    __shared__ float Y2s[8][128];
    __shared__ float oS[8][128];
    const int tid = threadIdx.x, r0 = blockIdx.x * 8;
    for (int i = tid; i < 8192; i += 256) Ws[i >> 6][i & 63] = W[i];
    const float* __restrict__ Y2 = Y + (size_t)n * 128;
    for (int i = tid; i < 1024; i += 256) {
        int r = i >> 7, c = i & 127;
        size_t gi = (size_t)(r0 + r) * 128 + c;
        Y1s[r][c] = Y[gi] + Y[gi + ps];
        Y2s[r][c] = Y2[gi] + Y2[gi + ps];
    }
    __syncthreads();
    const int c = tid & 127, rg = tid >> 7, d = c & 63, b64 = c & 64;
    const float bv = bias[d];
    for (int rr = rg; rr < 8; rr += 2) {
        float acc = bv;
#pragma unroll
        for (int k = 0; k < 64; k++) {
            acc = fmaf(Y1s[rr][b64 + k], Ws[k][d], acc);
            acc = fmaf(Y2s[rr][b64 + k], Ws[64 + k][d], acc);
        }
        float g = prev[(size_t)(r0 + rr) * 128 + c] + fmaxf(acc, 0.f);
        out[(size_t)(r0 + rr) * 128 + c] = g;
        oS[rr][c] = g;
    }
    __syncthreads();
    if (tid < 128) {
        float v[8];
#pragma unroll
        for (int j = 0; j < 8; j++) v[j] = oS[j][tid];
        *(uint4*)(Xf + (size_t)tid * n + r0) = pack8(v);
    }
}

// ===================== VNA epilogue =========================================
__global__ __launch_bounds__(256)
void epi_vna(const float* __restrict__ Y, const float* __restrict__ W,
             const float* __restrict__ bias, float* __restrict__ semb, int n, size_t ps)
{
    __shared__ float Ws[128][64];
    __shared__ float Y1s[8][128];
    __shared__ float Y2s[8][128];
    const int tid = threadIdx.x, r0 = blockIdx.x * 8, y = blockIdx.y;
    const float* __restrict__ Wp = W + y * 8192;
    const float* __restrict__ Y1 = Y + (size_t)(2 * y) * n * 128;
    const float* __restrict__ Y2 = Y1 + (size_t)n * 128;
    float* __restrict__ out = semb + (size_t)y * n * 128;
    for (int i = tid; i < 8192; i += 256) Ws[i >> 6][i & 63] = Wp[i];
    for (int i = tid; i < 1024; i += 256) {
        int r = i >> 7, c = i & 127;
        size_t gi = (size_t)(r0 + r) * 128 + c;
        Y1s[r][c] = Y1[gi] + Y1[gi + ps];
        Y2s[r][c] = Y2[gi] + Y2[gi + ps];
    }
    __syncthreads();
    const int c = tid & 127, rg = tid >> 7, d = c & 63, b64 = c & 64;
    const float bv = bias[y * 64 + d];
    for (int rr = rg; rr < 8; rr += 2) {
        float acc = bv;
#pragma unroll
        for (int k = 0; k < 64; k++) {
            acc = fmaf(Y1s[rr][b64 + k], Ws[k][d], acc);
            acc = fmaf(Y2s[rr][b64 + k], Ws[64 + k][d], acc);
        }
        out[(size_t)(r0 + rr) * 128 + c] = fmaxf(acc, 0.f);
    }
}

// ===================== target epilogue + gated fusion =======================
#define SMEM_TGT 49152
__global__ __launch_bounds__(256)
void epi_tgt(const float* __restrict__ Y, const float* __restrict__ W,
             const float* __restrict__ bias, const float* __restrict__ S,
             const float* __restrict__ fWt, const float* __restrict__ fWs,
             const float* __restrict__ fb, float* __restrict__ xt,
             u16* __restrict__ Xf, int n, size_t ps)
{
    extern __shared__ __align__(16) char dsm[];
    float* Wbuf = (float*)dsm;
    float (*Y1s)[128] = (float(*)[128])(dsm + 32768);
    float (*Y2s)[128] = (float(*)[128])(dsm + 36864);
    float (*tS)[128]  = (float(*)[128])(dsm + 40960);
    float (*sS)[128]  = (float(*)[128])(dsm + 45056);
    const int tid = threadIdx.x, r0 = blockIdx.x * 8;
    for (int i = tid; i < 8192; i += 256) Wbuf[i] = W[i];
    const float* __restrict__ Y2 = Y + (size_t)n * 128;
    for (int i = tid; i < 1024; i += 256) {
        int r = i >> 7, c = i & 127;
        size_t gi = (size_t)(r0 + r) * 128 + c;
        Y1s[r][c] = Y[gi] + Y[gi + ps];
        Y2s[r][c] = Y2[gi] + Y2[gi + ps];
        sS[r][c] = S[gi];
    }
    __syncthreads();
    const int c = tid & 127, rg = tid >> 7, d = c & 63, b64 = c & 64;
    const float bv = bias[d];
    for (int rr = rg; rr < 8; rr += 2) {
        float acc = bv;
#pragma unroll
        for (int k = 0; k < 64; k++) {
            acc = fmaf(Y1s[rr][b64 + k], Wbuf[k * 64 + d], acc);
            acc = fmaf(Y2s[rr][b64 + k], Wbuf[(64 + k) * 64 + d], acc);
        }
        tS[rr][c] = fmaxf(acc, 0.f);
    }
    __syncthreads();
    for (int i = tid; i < 4096; i += 256) { Wbuf[i] = fWt[i]; Wbuf[4096 + i] = fWs[i]; }
    __syncthreads();
    const float fbv = fb[d];
    for (int rr = rg; rr < 8; rr += 2) {
        float za = fbv;
#pragma unroll
        for (int k = 0; k < 64; k++) {
            za = fmaf(tS[rr][b64 + k], Wbuf[k * 64 + d], za);
            za = fmaf(sS[rr][b64 + k], Wbuf[4096 + k * 64 + d], za);
        }
        float z = 1.f / (1.f + expf(-za));
        float tv = tS[rr][c], sv = sS[rr][c];
        size_t gi = (size_t)(r0 + rr) * 128 + c;
        float nx = xt[gi] + z * tv + (1.f - z) * sv;
        xt[gi] = nx;
        Y1s[rr][c] = nx;
    }
    __syncthreads();
    if (Xf && tid < 128) {
        float v[8];
#pragma unroll
        for (int j = 0; j < 8; j++) v[j] = Y1s[j][tid];
        *(uint4*)(Xf + (size_t)tid * n + r0) = pack8(v);
    }
}

// ===================== launcher =============================================
extern "C" void kernel_launch(void* const* d_in, const int* in_sizes, int n_in,
                              void* d_out, int out_size)
{
    (void)in_sizes; (void)n_in; (void)out_size;
    const float* A0      = (const float*)d_in[0];
    const float* A1      = (const float*)d_in[1];
    const float* A2      = (const float*)d_in[2];
    const float* x0      = (const float*)d_in[3];
    const float* x1      = (const float*)d_in[4];
    const float* src_nv1 = (const float*)d_in[5];
    const float* src_nv2 = (const float*)d_in[6];
    const float* src_W   = (const float*)d_in[7];
    const float* src_b   = (const float*)d_in[8];
    const float* vna_nv1 = (const float*)d_in[9];
    const float* vna_nv2 = (const float*)d_in[10];
    const float* vna_W   = (const float*)d_in[11];
    const float* vna_b   = (const float*)d_in[12];
    const float* tgt_nv1 = (const float*)d_in[13];
    const float* tgt_nv2 = (const float*)d_in[14];
    const float* tgt_W   = (const float*)d_in[15];
    const float* tgt_b   = (const float*)d_in[16];
    const float* fus_Wt  = (const float*)d_in[17];
    const float* fus_Ws  = (const float*)d_in[18];
    const float* fus_b   = (const float*)d_in[19];

    u16 *A0f, *A1f, *A2f, *Es, *Ev, *Et, *Xf;
    unsigned* Mrow;
    float *psum, *src_inv, *vna_inv, *tgt_inv, *lr, *semb, *Yb, *xtb;
    cudaGetSymbolAddress((void**)&A0f, g_A0f);
    cudaGetSymbolAddress((void**)&A1f, g_A1f);
    cudaGetSymbolAddress((void**)&A2f, g_A2f);
    cudaGetSymbolAddress((void**)&Es, g_Es);
    cudaGetSymbolAddress((void**)&Ev, g_Ev);
    cudaGetSymbolAddress((void**)&Et, g_Et);
    cudaGetSymbolAddress((void**)&Xf, g_Xf);
    cudaGetSymbolAddress((void**)&Mrow, g_Mrow);
    cudaGetSymbolAddress((void**)&psum, g_psum);
    cudaGetSymbolAddress((void**)&src_inv, g_src_inv);
    cudaGetSymbolAddress((void**)&vna_inv, g_vna_inv);
    cudaGetSymbolAddress((void**)&tgt_inv, g_tgt_inv);
    cudaGetSymbolAddress((void**)&lr, g_lr);
    cudaGetSymbolAddress((void**)&semb, g_semb);
    cudaGetSymbolAddress((void**)&Yb, g_Y);
    cudaGetSymbolAddress((void**)&xtb, g_xt);

    cudaFuncSetAttribute(hmma_gemm3m, cudaFuncAttributeMaxDynamicSharedMemorySize, SMEM_GEMM);
    cudaFuncSetAttribute(epi_tgt, cudaFuncAttributeMaxDynamicSharedMemorySize, SMEM_TGT);
    cudaFuncSetAttribute(adp_pass<0>, cudaFuncAttributeMaxDynamicSharedMemorySize, ADPSM);
    cudaFuncSetAttribute(adp_pass<1>, cudaFuncAttributeMaxDynamicSharedMemorySize, ADPSM);

    const size_t SLOT = (size_t)128 * NS;
    u16* Xf3 = Xf + 3 * SLOT;
    const int xS = ((NS + 31) / 32) * 2;   // 314
    const int xT = ((NT + 31) / 32) * 2;   // 250
    const int mhS = 2560, mhT = 2048;
    const size_t psS = (size_t)2 * NS * 128;
    const size_t psT1 = (size_t)2 * NT * 128;
    const size_t psT3 = (size_t)6 * NT * 128;
    const int gS = (NS + 63) / 64, gT = (NT + 63) / 64;   // 79, 63

    // ---- src chain ----
    pack_prep<<<NS / 8, 256>>>(x1, lr, Xf, NS);
    tofp16_kernel<<<(NS * NS / 4 + 255) / 256, 256>>>(A2, A2f, NS * NS / 4);
    zero_u<<<(NS + 255) / 256, 256>>>(Mrow, NS);
    adp_pass<0><<<dim3(gS, ADPCS), 256, ADPSM>>>(src_nv1, src_nv2, Mrow, (u16*)nullptr, (float*)nullptr, NS, NS);
    adp_pass<1><<<dim3(gS, ADPCS), 256, ADPSM>>>(src_nv1, src_nv2, Mrow, Es, psum, NS, NS);
    adp_inv<<<(NS + 255) / 256, 256>>>(psum, src_inv, NS);
    for (int i = 0; i < 2; i++) {
        hmma_gemm3m<<<dim3(xS, 2), 128, SMEM_GEMM>>>(A2f, Es, src_inv,
            Xf + i * SLOT, Yb, NS, NS, mhS, 1);
        epi_src<<<NS / 8, 256>>>(Yb, src_W + i * 8192, src_b + i * 64,
            lr + (size_t)i * NS * 128, lr + (size_t)(i + 1) * NS * 128,
            Xf + (i + 1) * SLOT, NS, psS);
    }

    // ---- rest of prep ----
    pack_prep<<<NT / 8, 256>>>(x0, xtb, Xf3, NT);
    tofp16_kernel<<<(NT * NT / 4 + 255) / 256, 256>>>(A0, A0f, NT * NT / 4);
    tofp16_kernel<<<(NT * NS / 4 + 255) / 256, 256>>>(A1, A1f, NT * NS / 4);
    zero_u<<<(NT + 255) / 256, 256>>>(Mrow, NT);
    adp_pass<0><<<dim3(gT, ADPCS), 256, ADPSM>>>(vna_nv1, vna_nv2, Mrow, (u16*)nullptr, (float*)nullptr, NT, NS);
    adp_pass<1><<<dim3(gT, ADPCS), 256, ADPSM>>>(vna_nv1, vna_nv2, Mrow, Ev, psum, NT, NS);
    adp_inv<<<(NT + 255) / 256, 256>>>(psum, vna_inv, NT);
    zero_u<<<(NT + 255) / 256, 256>>>(Mrow, NT);
    adp_pass<0><<<dim3(gT, ADPCS), 256, ADPSM>>>(tgt_nv1, tgt_nv2, Mrow, (u16*)nullptr, (float*)nullptr, NT, NT);
    adp_pass<1><<<dim3(gT, ADPCS), 256, ADPSM>>>(tgt_nv1, tgt_nv2, Mrow, Et, psum, NT, NT);
    adp_inv<<<(NT + 255) / 256, 256>>>(psum, tgt_inv, NT);

    // ---- VNA block: 3 layers batched, K-split 2 ----
    hmma_gemm3m<<<dim3(xT, 6), 128, SMEM_GEMM>>>(A1f, Ev, vna_inv, Xf, Yb, NT, NS, mhS, 3);
    epi_vna<<<dim3(NT / 8, 3), 256>>>(Yb, vna_W, vna_b, semb, NT, psT3);

    // ---- Target GC block with gated fusion ----
    for (int i = 0; i < 3; i++) {
        hmma_gemm3m<<<dim3(xT, 2), 128, SMEM_GEMM>>>(A0f, Et, tgt_inv, Xf3, Yb, NT, NT, mhT, 1);
        epi_tgt<<<NT / 8, 256, SMEM_TGT>>>(Yb, tgt_W + i * 8192, tgt_b + i * 64,
            semb + (size_t)i * NT * 128, fus_Wt + i * 4096, fus_Ws + i * 4096,
            fus_b + i * 64, xtb, (i < 2) ? Xf3 : (u16*)nullptr, NT, psT1);
    }

    unpack_kernel<<<(NT * 128 + 255) / 256, 256>>>(xtb, (float*)d_out, NT);
}

// round 14
// speedup vs baseline: 1.5257x; 1.1107x over previous
#include <cuda_runtime.h>
#include <cuda_fp16.h>
#include <math.h>
#include <stdint.h>

#define NT 4000
#define NS 5000
#define LOG2E 1.4426950408889634f
typedef unsigned short u16;

// ===================== scratch =============================================
__device__ __align__(16) u16 g_A0f[16000000];
__device__ __align__(16) u16 g_A1f[20000000];
__device__ __align__(16) u16 g_A2f[25000000];
__device__ __align__(16) u16 g_Es[25000000];
__device__ __align__(16) u16 g_Ev[20000000];
__device__ __align__(16) u16 g_Et[16000000];
__device__ __align__(16) u16 g_Xf[2432000];
__device__ __align__(16) u16 g_nv1h[163840], g_nv1l[163840];
__device__ __align__(16) u16 g_nv2h[163840], g_nv2l[163840];
__device__ unsigned g_Mrow[5120];
__device__ float g_psum[40960];
__device__ float g_src_inv[NS];
__device__ float g_vna_inv[NT];
__device__ float g_tgt_inv[NT];
__device__ __align__(16) float g_lr[3 * NS * 128];
__device__ __align__(16) float g_semb[3 * NT * 128];
__device__ __align__(16) float g_Y[6200000];
__device__ __align__(16) float g_xt[NT * 128];

// ===================== PTX helpers =========================================
__device__ __forceinline__ uint32_t smem_u32(const void* p) {
    uint32_t a;
    asm("{ .reg .u64 t; cvta.to.shared.u64 t, %1; cvt.u32.u64 %0, t; }" : "=r"(a) : "l"(p));
    return a;
}
#define CP_ASYNC16(saddr, gaddr, sz) \
    asm volatile("cp.async.ca.shared.global [%0], [%1], 16, %2;" :: "r"(saddr), "l"(gaddr), "r"(sz))
#define CP_COMMIT() asm volatile("cp.async.commit_group;" ::: "memory")
#define CP_WAIT1()  asm volatile("cp.async.wait_group 1;" ::: "memory")
#define CP_WAIT0()  asm volatile("cp.async.wait_group 0;" ::: "memory")
#define LDSM4(r, a) \
    asm volatile("ldmatrix.sync.aligned.m8n8.x4.shared.b16 {%0,%1,%2,%3}, [%4];" \
        : "=r"((r)[0]), "=r"((r)[1]), "=r"((r)[2]), "=r"((r)[3]) : "r"(a))
#define MMA_FP16(c, A, b0, b1) \
    asm volatile("mma.sync.aligned.m16n8k16.row.col.f32.f16.f16.f32 " \
        "{%0,%1,%2,%3},{%4,%5,%6,%7},{%8,%9},{%0,%1,%2,%3};" \
        : "+f"((c)[0]), "+f"((c)[1]), "+f"((c)[2]), "+f"((c)[3]) \
        : "r"((A)[0]), "r"((A)[1]), "r"((A)[2]), "r"((A)[3]), "r"(b0), "r"(b1))

__device__ __forceinline__ uint32_t pack_h2(float a, float b) {
    return (uint32_t)__half_as_ushort(__float2half_rn(a)) |
           ((uint32_t)__half_as_ushort(__float2half_rn(b)) << 16);
}
__device__ __forceinline__ uint4 pack8(const float* v) {
    uint4 H;
    H.x = pack_h2(v[0], v[1]); H.y = pack_h2(v[2], v[3]);
    H.z = pack_h2(v[4], v[5]); H.w = pack_h2(v[6], v[7]);
    return H;
}
__device__ __forceinline__ uint32_t swz(uint32_t x) { return x ^ ((x >> 3) & 0x70); }

// ===================== small kernels ========================================
__global__ void zero_u(unsigned* p, int n) {
    int i = blockIdx.x * blockDim.x + threadIdx.x;
    if (i < n) p[i] = 0u;
}
__global__ void unpack_kernel(const float* __restrict__ xp, float* __restrict__ out, int n) {
    int i = blockIdx.x * blockDim.x + threadIdx.x;
    if (i >= n * 128) return;
    int r = i >> 7, c = i & 127, b = c >> 6, d = c & 63;
    out[((size_t)b * n + r) * 64 + d] = xp[i];
}
__global__ void tofp16_kernel(const float* __restrict__ A, u16* __restrict__ F, int n4) {
    int i = blockIdx.x * blockDim.x + threadIdx.x;
    if (i >= n4) return;
    float4 v = ((const float4*)A)[i];
    uint2 o;
    o.x = pack_h2(v.x * 4096.f, v.y * 4096.f);
    o.y = pack_h2(v.z * 4096.f, v.w * 4096.f);
    ((uint2*)F)[i] = o;
}
__global__ __launch_bounds__(256)
void pack_prep(const float* __restrict__ x, float* __restrict__ xp,
               u16* __restrict__ Xf, int n)
{
    __shared__ float t[8][128];
    const int tid = threadIdx.x, r0 = blockIdx.x * 8;
    for (int i = tid; i < 1024; i += 256) {
        int r = i >> 7, c = i & 127, b = c >> 6, d = c & 63;
        float v = x[((size_t)b * n + r0 + r) * 64 + d];
        xp[(size_t)(r0 + r) * 128 + c] = v;
        t[r][c] = v;
    }
    __syncthreads();
    if (tid < 128) {
        float v[8];
#pragma unroll
        for (int j = 0; j < 8; j++) v[j] = t[j][tid];
        *(uint4*)(Xf + (size_t)tid * n + r0) = pack8(v);
    }
}
// nv1 [n][30] -> hi/lo [n][32] fp16
__global__ void nv1_prep(const float* __restrict__ nv1, u16* __restrict__ h,
                         u16* __restrict__ l, int n) {
    int i = blockIdx.x * blockDim.x + threadIdx.x;
    if (i >= n * 32) return;
    int r = i >> 5, q = i & 31;
    float v = (q < 30) ? nv1[(size_t)r * 30 + q] : 0.f;
    __half hh = __float2half_rn(v);
    h[i] = __half_as_ushort(hh);
    l[i] = __half_as_ushort(__float2half_rn(v - __half2float(hh)));
}
// nv2 [30][ncols] -> transposed hi/lo [ncols][32] fp16
__global__ void nv2_prep(const float* __restrict__ nv2, u16* __restrict__ h,
                         u16* __restrict__ l, int ncols) {
    int c = blockIdx.x * blockDim.x + threadIdx.x;
    if (c >= ncols) return;
    u16 hb[32], lb[32];
#pragma unroll
    for (int q = 0; q < 32; q++) {
        float v = (q < 30) ? nv2[(size_t)q * ncols + c] : 0.f;
        __half hh = __float2half_rn(v);
        hb[q] = __half_as_ushort(hh);
        lb[q] = __half_as_ushort(__float2half_rn(v - __half2float(hh)));
    }
#pragma unroll
    for (int j = 0; j < 4; j++) {
        ((uint4*)(h + (size_t)c * 32))[j] = ((uint4*)hb)[j];
        ((uint4*)(l + (size_t)c * 32))[j] = ((uint4*)lb)[j];
    }
}

// ===================== adaptive adjacency via tensor cores ==================
// grid (rowtiles, CS): CTA = 64 rows x column slice. Operands pre-converted fp16.
// MODE 0: hi-only approx max -> atomicMax. MODE 1: 3-pass E fp16 + psum slot.
#define ADPCS 8
#define ADPSM 49152   // Ah 8K | Al 8K | Bh 16K | Bl 16K
template<int MODE>
__global__ __launch_bounds__(256, 2)
void adp_pass(const u16* __restrict__ nv1h, const u16* __restrict__ nv1l,
              const u16* __restrict__ nv2h, const u16* __restrict__ nv2l,
              unsigned* __restrict__ Mrow_g, u16* __restrict__ E,
              float* __restrict__ psum, int nrows, int ncols)
{
    extern __shared__ __align__(128) char dsm[];
    __shared__ float redbuf[2][64];
    __shared__ float MrowS[64];
    const uint32_t sA = smem_u32(dsm), sAl = sA + 8192, sB = sA + 16384, sBl = sA + 32768;
    const int tid = threadIdx.x, lane = tid & 31, wid = tid >> 5;
    const int wm = wid >> 1, wn = wid & 1;
    const int r0 = blockIdx.x * 64, cy = blockIdx.y;

    // A tiles via cp.async (row r: 64B = 4 chunks)
    {
        int r = tid >> 2, cch = tid & 3;
        int gr = r0 + r;
        bool v = gr < nrows;
        size_t gi = (size_t)(v ? gr : 0) * 32 + cch * 8;
        uint32_t sw = swz((uint32_t)r * 128 + cch * 16);
        CP_ASYNC16(sA + sw, nv1h + gi, v ? 16u : 0u);
        if (MODE == 1) CP_ASYNC16(sAl + sw, nv1l + gi, v ? 16u : 0u);
    }
    CP_COMMIT();
    if (MODE == 1 && tid < 64)
        MrowS[tid] = (r0 + tid < nrows) ? __uint_as_float(Mrow_g[r0 + tid]) : 0.f;

    uint32_t arow, axor;
    { int r = wm * 16 + (lane & 7) + (((lane >> 3) & 1) << 3);
      arow = (uint32_t)r * 128; axor = ((uint32_t)r * 16) & 0x70; }
    const uint32_t akbs = ((lane >> 4) & 1) * 16;
    uint32_t brow[4], bxor[4];
#pragma unroll
    for (int bt = 0; bt < 4; bt++) {
        int r = wn * 64 + bt * 16 + (lane & 7) + (((lane >> 4) & 1) << 3);
        brow[bt] = (uint32_t)r * 128; bxor[bt] = ((uint32_t)r * 16) & 0x70;
    }
    const uint32_t bkbs = ((lane >> 3) & 1) * 16;

    const int gr0 = r0 + wm * 16 + (lane >> 2), gr1 = gr0 + 8;
    float mx0 = 0.f, mx1 = 0.f, ps0 = 0.f, ps1 = 0.f;
    float M0 = 0.f, M1 = 0.f;

    const int nch = (ncols + 127) / 128;
    const int cper = (nch + ADPCS - 1) / ADPCS;
    const int chLo = cy * cper, chHi = min(nch, chLo + cper);
    bool mInit = false;
    for (int ch = chLo; ch < chHi; ch++) {
        const int c0 = ch * 128;
        __syncthreads();   // smem B reuse safety
        // B tiles via cp.async (col j: 64B = 4 chunks, 512 per plane)
#pragma unroll
        for (int t = 0; t < 2; t++) {
            int id = tid + t * 256;
            int j = id >> 2, cch = id & 3;
            int c = c0 + j;
            bool v = c < ncols;
            size_t gi = (size_t)(v ? c : 0) * 32 + cch * 8;
            uint32_t sw = swz((uint32_t)j * 128 + cch * 16);
            CP_ASYNC16(sB + sw, nv2h + gi, v ? 16u : 0u);
            if (MODE == 1) CP_ASYNC16(sBl + sw, nv2l + gi, v ? 16u : 0u);
        }
        CP_COMMIT();
        CP_WAIT0();
        __syncthreads();
        if (MODE == 1 && !mInit) {
            M0 = MrowS[wm * 16 + (lane >> 2)];
            M1 = MrowS[wm * 16 + (lane >> 2) + 8];
            mInit = true;
        }

        float acc[8][4];
#pragma unroll
        for (int j = 0; j < 8; j++)
#pragma unroll
            for (int q = 0; q < 4; q++) acc[j][q] = 0.f;
#pragma unroll
        for (int ks = 0; ks < 2; ks++) {
            const uint32_t kb = ks * 32;
            uint32_t fah[4], fal[4], fbh[4][4], fbl[4][4];
            LDSM4(fah, sA + arow + ((kb + akbs) ^ axor));
            if (MODE == 1) LDSM4(fal, sAl + arow + ((kb + akbs) ^ axor));
#pragma unroll
            for (int bt = 0; bt < 4; bt++) {
                LDSM4(fbh[bt], sB + brow[bt] + ((kb + bkbs) ^ bxor[bt]));
                if (MODE == 1) LDSM4(fbl[bt], sBl + brow[bt] + ((kb + bkbs) ^ bxor[bt]));
            }
#pragma unroll
            for (int nt = 0; nt < 8; nt++) {
                const int g = nt >> 1, h = (nt & 1) << 1;
                MMA_FP16(acc[nt], fah, fbh[g][h], fbh[g][h + 1]);
                if (MODE == 1) {
                    MMA_FP16(acc[nt], fah, fbl[g][h], fbl[g][h + 1]);
                    MMA_FP16(acc[nt], fal, fbh[g][h], fbh[g][h + 1]);
                }
            }
        }

#pragma unroll
        for (int nt = 0; nt < 8; nt++) {
            int c = c0 + wn * 64 + nt * 8 + ((lane & 3) << 1);
            float d00 = fmaxf(acc[nt][0], 0.f), d01 = fmaxf(acc[nt][1], 0.f);
            float d10 = fmaxf(acc[nt][2], 0.f), d11 = fmaxf(acc[nt][3], 0.f);
            if (MODE == 0) {
                if (c < ncols) {
                    mx0 = fmaxf(mx0, fmaxf(d00, d01));
                    mx1 = fmaxf(mx1, fmaxf(d10, d11));
                }
            } else {
                __half2 h0 = __floats2half2_rn((d00 - M0) * LOG2E, (d01 - M0) * LOG2E);
                __half2 h1 = __floats2half2_rn((d10 - M1) * LOG2E, (d11 - M1) * LOG2E);
                uint32_t e0, e1;
                asm("ex2.approx.f16x2 %0, %1;" : "=r"(e0) : "r"(*(uint32_t*)&h0));
                asm("ex2.approx.f16x2 %0, %1;" : "=r"(e1) : "r"(*(uint32_t*)&h1));
                if (c < ncols) {
                    float2 f0 = __half22float2(*(__half2*)&e0);
                    float2 f1 = __half22float2(*(__half2*)&e1);
                    ps0 += f0.x + f0.y;
                    ps1 += f1.x + f1.y;
                    if (gr0 < nrows) *(uint32_t*)(E + (size_t)gr0 * ncols + c) = e0;
                    if (gr1 < nrows) *(uint32_t*)(E + (size_t)gr1 * ncols + c) = e1;
                }
            }
        }
    }

    float v0 = (MODE == 0) ? mx0 : ps0, v1 = (MODE == 0) ? mx1 : ps1;
#pragma unroll
    for (int off = 1; off <= 2; off <<= 1) {
        float o0 = __shfl_xor_sync(0xffffffffu, v0, off);
        float o1 = __shfl_xor_sync(0xffffffffu, v1, off);
        if (MODE == 0) { v0 = fmaxf(v0, o0); v1 = fmaxf(v1, o1); }
        else           { v0 += o0;           v1 += o1; }
    }
    if ((lane & 3) == 0) {
        redbuf[wn][wm * 16 + (lane >> 2)] = v0;
        redbuf[wn][wm * 16 + (lane >> 2) + 8] = v1;
    }
    __syncthreads();
    if (tid < 64 && r0 + tid < nrows) {
        float a = redbuf[0][tid], b = redbuf[1][tid];
        if (MODE == 0)
            atomicMax(Mrow_g + r0 + tid, __float_as_uint(fmaxf(a, b)));  // >=0: bit order == float order
        else
            psum[(size_t)(r0 + tid) * ADPCS + cy] = a + b;
    }
}

__global__ void adp_inv(const float* __restrict__ psum, float* __restrict__ inv, int nrows) {
    int r = blockIdx.x * blockDim.x + threadIdx.x;
    if (r >= nrows) return;
    float s = 0.f;
#pragma unroll
    for (int q = 0; q < ADPCS; q++) s += psum[(size_t)r * ADPCS + q];
    inv[r] = 1.0f / s;
}

// ===================== merged-support split-K HMMA GEMM (R10 config) ========
#define GKT 64
#define STAGE_B 16384
#define SMEM_GEMM (2 * STAGE_B)

__device__ __forceinline__ void stage_ldm(uint32_t sdst,
    const u16* __restrict__ Ad, const u16* __restrict__ Ae, const u16* __restrict__ B,
    int row0, int kbase, int n, int kend, int m, int tid)
{
#pragma unroll
    for (int t = 0; t < 2; t++) {
        int id = tid + t * 128;
        int r = id >> 3, kc = id & 7;
        int gr = row0 + r, gk = kbase + kc * 8;
        bool v = (gr < n) && (gk < kend);
        size_t gi = (size_t)(v ? gr : 0) * m + (v ? gk : 0);
        uint32_t sw = swz(r * 128 + kc * 16);
        unsigned sz = v ? 16u : 0u;
        CP_ASYNC16(sdst + sw, Ad + gi, sz);
        CP_ASYNC16(sdst + 4096 + sw, Ae + gi, sz);
    }
#pragma unroll
    for (int t = 0; t < 4; t++) {
        int id = tid + t * 128;
        int cr = id >> 3, kc = id & 7;
        int gk = kbase + kc * 8;
        bool v = (gk < kend);
        size_t gi = (size_t)cr * m + (v ? gk : 0);
        uint32_t sw = swz(cr * 128 + kc * 16);
        CP_ASYNC16(sdst + 8192 + sw, B + gi, v ? 16u : 0u);
    }
}

__global__ __launch_bounds__(128, 4)
void hmma_gemm3m(const u16* __restrict__ Af, const u16* __restrict__ Ef,
                 const float* __restrict__ invsum,
                 const u16* __restrict__ Xf,
                 float* __restrict__ Y, int n, int m, int mh, int ny)
{
    extern __shared__ __align__(128) char smem[];
    const uint32_t sb = smem_u32(smem);
    const int tid = threadIdx.x, lane = tid & 31, wid = tid >> 5;
    const int wm = wid >> 1, wn = wid & 1;
    const int tile = blockIdx.x >> 1, nh = blockIdx.x & 1;
    const int row0 = tile * 32, col0 = nh * 64;
    const int yb = blockIdx.y % ny, zs = blockIdx.y / ny;
    const u16* __restrict__ B = Xf + ((size_t)yb * 128 + col0) * m;
    const int k0 = zs * mh, kend = min(m, k0 + mh);
    const int ktn = (kend - k0 + GKT - 1) / GKT;

    float accD[4][4], accE[4][4];
#pragma unroll
    for (int j = 0; j < 4; j++)
#pragma unroll
        for (int q = 0; q < 4; q++) { accD[j][q] = 0.f; accE[j][q] = 0.f; }

    uint32_t arow, axor;
    { int r = wm * 16 + (lane & 7) + (((lane >> 3) & 1) << 3);
      arow = (uint32_t)r * 128; axor = ((uint32_t)r * 16) & 0x70; }
    const uint32_t akbs = ((lane >> 4) & 1) * 16;
    uint32_t brow[2], bxor[2];
#pragma unroll
    for (int bt = 0; bt < 2; bt++) {
        int r = wn * 32 + bt * 16 + (lane & 7) + (((lane >> 4) & 1) << 3);
        brow[bt] = (uint32_t)r * 128; bxor[bt] = ((uint32_t)r * 16) & 0x70;
    }
    const uint32_t bkbs = ((lane >> 3) & 1) * 16;

    stage_ldm(sb, Af, Ef, B, row0, k0, n, kend, m, tid);
    CP_COMMIT();

    for (int kt = 0; kt < ktn; kt++) {
        if (kt + 1 < ktn)
            stage_ldm(sb + ((kt + 1) & 1) * STAGE_B, Af, Ef, B,
                      row0, k0 + (kt + 1) * GKT, n, kend, m, tid);
        CP_COMMIT();
        CP_WAIT1();
        __syncthreads();
        const uint32_t stb = sb + (kt & 1) * STAGE_B;
#pragma unroll
        for (int ks = 0; ks < 4; ks++) {
            const uint32_t kb = ks * 32;
            uint32_t fad[4], fae[4], fb[2][4];
            LDSM4(fad, stb + arow + ((kb + akbs) ^ axor));
            LDSM4(fae, stb + 4096 + arow + ((kb + akbs) ^ axor));
#pragma unroll
            for (int bt = 0; bt < 2; bt++)
                LDSM4(fb[bt], stb + 8192 + brow[bt] + ((kb + bkbs) ^ bxor[bt]));
#pragma unroll
            for (int nt = 0; nt < 4; nt++) {
                const int g = nt >> 1, h = (nt & 1) << 1;
                MMA_FP16(accD[nt], fad, fb[g][h], fb[g][h + 1]);
                MMA_FP16(accE[nt], fae, fb[g][h], fb[g][h + 1]);
            }
        }
        __syncthreads();
    }

    float* __restrict__ Yd = Y + (size_t)(zs * 2 * ny + yb * 2) * n * 128;
    float* __restrict__ Ye = Yd + (size_t)n * 128;
    const int gr0 = row0 + wm * 16 + (lane >> 2), gr1 = gr0 + 8;
    const float SD = 2.44140625e-4f;
    const float e0 = (gr0 < n) ? invsum[gr0] : 0.f;
    const float e1 = (gr1 < n) ? invsum[gr1] : 0.f;
#pragma unroll
    for (int nt = 0; nt < 4; nt++) {
        int col = col0 + wn * 32 + nt * 8 + ((lane & 3) << 1);
        if (gr0 < n) {
            *(float2*)(Yd + (size_t)gr0 * 128 + col) =
                make_float2(accD[nt][0] * SD, accD[nt][1] * SD);
            *(float2*)(Ye + (size_t)gr0 * 128 + col) =
                make_float2(accE[nt][0] * e0, accE[nt][1] * e0);
        }
        if (gr1 < n) {
            *(float2*)(Yd + (size_t)gr1 * 128 + col) =
                make_float2(accD[nt][2] * SD, accD[nt][3] * SD);
            *(float2*)(Ye + (size_t)gr1 * 128 + col) =
                make_float2(accE[nt][2] * e1, accE[nt][3] * e1);
        }
    }
}

// ===================== source epilogue ======================================
__global__ __launch_bounds__(256)
void epi_src(const float* __restrict__ Y, const float* __restrict__ W,
             const float* __restrict__ bias, const float* __restrict__ prev,
             float* __restrict__ out, u16* __restrict__ Xf, int n, size_t ps)
{
    __shared__ float Ws[128][64];
    __shared__ float Y1s[8][128];
    __shared__ float Y2s[8][128];
    __shared__ float oS[8][128];
    const int tid = threadIdx.x, r0 = blockIdx.x * 8;
    for (int i = tid; i < 8192; i += 256) Ws[i >> 6][i & 63] = W[i];
    const float* __restrict__ Y2 = Y + (size_t)n * 128;
    for (int i = tid; i < 1024; i += 256) {
        int r = i >> 7, c = i & 127;
        size_t gi = (size_t)(r0 + r) * 128 + c;
        Y1s[r][c] = Y[gi] + Y[gi + ps];
        Y2s[r][c] = Y2[gi] + Y2[gi + ps];
    }
    __syncthreads();
    const int c = tid & 127, rg = tid >> 7, d = c & 63, b64 = c & 64;
    const float bv = bias[d];
    for (int rr = rg; rr < 8; rr += 2) {
        float acc = bv;
#pragma unroll
        for (int k = 0; k < 64; k++) {
            acc = fmaf(Y1s[rr][b64 + k], Ws[k][d], acc);
            acc = fmaf(Y2s[rr][b64 + k], Ws[64 + k][d], acc);
        }
        float g = prev[(size_t)(r0 + rr) * 128 + c] + fmaxf(acc, 0.f);
        out[(size_t)(r0 + rr) * 128 + c] = g;
        oS[rr][c] = g;
    }
    __syncthreads();
    if (tid < 128) {
        float v[8];
#pragma unroll
        for (int j = 0; j < 8; j++) v[j] = oS[j][tid];
        *(uint4*)(Xf + (size_t)tid * n + r0) = pack8(v);
    }
}

// ===================== VNA epilogue =========================================
__global__ __launch_bounds__(256)
void epi_vna(const float* __restrict__ Y, const float* __restrict__ W,
             const float* __restrict__ bias, float* __restrict__ semb, int n, size_t ps)
{
    __shared__ float Ws[128][64];
    __shared__ float Y1s[8][128];
    __shared__ float Y2s[8][128];
    const int tid = threadIdx.x, r0 = blockIdx.x * 8, y = blockIdx.y;
    const float* __restrict__ Wp = W + y * 8192;
    const float* __restrict__ Y1 = Y + (size_t)(2 * y) * n * 128;
    const float* __restrict__ Y2 = Y1 + (size_t)n * 128;
    float* __restrict__ out = semb + (size_t)y * n * 128;
    for (int i = tid; i < 8192; i += 256) Ws[i >> 6][i & 63] = Wp[i];
    for (int i = tid; i < 1024; i += 256) {
        int r = i >> 7, c = i & 127;
        size_t gi = (size_t)(r0 + r) * 128 + c;
        Y1s[r][c] = Y1[gi] + Y1[gi + ps];
        Y2s[r][c] = Y2[gi] + Y2[gi + ps];
    }
    __syncthreads();
    const int c = tid & 127, rg = tid >> 7, d = c & 63, b64 = c & 64;
    const float bv = bias[y * 64 + d];
    for (int rr = rg; rr < 8; rr += 2) {
        float acc = bv;
#pragma unroll
        for (int k = 0; k < 64; k++) {
            acc = fmaf(Y1s[rr][b64 + k], Ws[k][d], acc);
            acc = fmaf(Y2s[rr][b64 + k], Ws[64 + k][d], acc);
        }
        out[(size_t)(r0 + rr) * 128 + c] = fmaxf(acc, 0.f);
    }
}

// ===================== target epilogue + gated fusion =======================
#define SMEM_TGT 49152
__global__ __launch_bounds__(256)
void epi_tgt(const float* __restrict__ Y, const float* __restrict__ W,
             const float* __restrict__ bias, const float* __restrict__ S,
             const float* __restrict__ fWt, const float* __restrict__ fWs,
             const float* __restrict__ fb, float* __restrict__ xt,
             u16* __restrict__ Xf, int n, size_t ps)
{
    extern __shared__ __align__(16) char dsm[];
    float* Wbuf = (float*)dsm;
    float (*Y1s)[128] = (float(*)[128])(dsm + 32768);
    float (*Y2s)[128] = (float(*)[128])(dsm + 36864);
    float (*tS)[128]  = (float(*)[128])(dsm + 40960);
    float (*sS)[128]  = (float(*)[128])(dsm + 45056);
    const int tid = threadIdx.x, r0 = blockIdx.x * 8;
    for (int i = tid; i < 8192; i += 256) Wbuf[i] = W[i];
    const float* __restrict__ Y2 = Y + (size_t)n * 128;
    for (int i = tid; i < 1024; i += 256) {
        int r = i >> 7, c = i & 127;
        size_t gi = (size_t)(r0 + r) * 128 + c;
        Y1s[r][c] = Y[gi] + Y[gi + ps];
        Y2s[r][c] = Y2[gi] + Y2[gi + ps];
        sS[r][c] = S[gi];
    }
    __syncthreads();
    const int c = tid & 127, rg = tid >> 7, d = c & 63, b64 = c & 64;
    const float bv = bias[d];
    for (int rr = rg; rr < 8; rr += 2) {
        float acc = bv;
#pragma unroll
        for (int k = 0; k < 64; k++) {
            acc = fmaf(Y1s[rr][b64 + k], Wbuf[k * 64 + d], acc);
            acc = fmaf(Y2s[rr][b64 + k], Wbuf[(64 + k) * 64 + d], acc);
        }
        tS[rr][c] = fmaxf(acc, 0.f);
    }
    __syncthreads();
    for (int i = tid; i < 4096; i += 256) { Wbuf[i] = fWt[i]; Wbuf[4096 + i] = fWs[i]; }
    __syncthreads();
    const float fbv = fb[d];
    for (int rr = rg; rr < 8; rr += 2) {
        float za = fbv;
#pragma unroll
        for (int k = 0; k < 64; k++) {
            za = fmaf(tS[rr][b64 + k], Wbuf[k * 64 + d], za);
            za = fmaf(sS[rr][b64 + k], Wbuf[4096 + k * 64 + d], za);
        }
        float z = 1.f / (1.f + expf(-za));
        float tv = tS[rr][c], sv = sS[rr][c];
        size_t gi = (size_t)(r0 + rr) * 128 + c;
        float nx = xt[gi] + z * tv + (1.f - z) * sv;
        xt[gi] = nx;
        Y1s[rr][c] = nx;
    }
    __syncthreads();
    if (Xf && tid < 128) {
        float v[8];
#pragma unroll
        for (int j = 0; j < 8; j++) v[j] = Y1s[j][tid];
        *(uint4*)(Xf + (size_t)tid * n + r0) = pack8(v);
    }
}

// ===================== launcher =============================================
extern "C" void kernel_launch(void* const* d_in, const int* in_sizes, int n_in,
                              void* d_out, int out_size)
{
    (void)in_sizes; (void)n_in; (void)out_size;
    const float* A0      = (const float*)d_in[0];
    const float* A1      = (const float*)d_in[1];
    const float* A2      = (const float*)d_in[2];
    const float* x0      = (const float*)d_in[3];
    const float* x1      = (const float*)d_in[4];
    const float* src_nv1 = (const float*)d_in[5];
    const float* src_nv2 = (const float*)d_in[6];
    const float* src_W   = (const float*)d_in[7];
    const float* src_b   = (const float*)d_in[8];
    const float* vna_nv1 = (const float*)d_in[9];
    const float* vna_nv2 = (const float*)d_in[10];
    const float* vna_W   = (const float*)d_in[11];
    const float* vna_b   = (const float*)d_in[12];
    const float* tgt_nv1 = (const float*)d_in[13];
    const float* tgt_nv2 = (const float*)d_in[14];
    const float* tgt_W   = (const float*)d_in[15];
    const float* tgt_b   = (const float*)d_in[16];
    const float* fus_Wt  = (const float*)d_in[17];
    const float* fus_Ws  = (const float*)d_in[18];
    const float* fus_b   = (const float*)d_in[19];

    u16 *A0f, *A1f, *A2f, *Es, *Ev, *Et, *Xf, *nv1h, *nv1l, *nv2h, *nv2l;
    unsigned* Mrow;
    float *psum, *src_inv, *vna_inv, *tgt_inv, *lr, *semb, *Yb, *xtb;
    cudaGetSymbolAddress((void**)&A0f, g_A0f);
    cudaGetSymbolAddress((void**)&A1f, g_A1f);
    cudaGetSymbolAddress((void**)&A2f, g_A2f);
    cudaGetSymbolAddress((void**)&Es, g_Es);
    cudaGetSymbolAddress((void**)&Ev, g_Ev);
    cudaGetSymbolAddress((void**)&Et, g_Et);
    cudaGetSymbolAddress((void**)&Xf, g_Xf);
    cudaGetSymbolAddress((void**)&nv1h, g_nv1h);
    cudaGetSymbolAddress((void**)&nv1l, g_nv1l);
    cudaGetSymbolAddress((void**)&nv2h, g_nv2h);
    cudaGetSymbolAddress((void**)&nv2l, g_nv2l);
    cudaGetSymbolAddress((void**)&Mrow, g_Mrow);
    cudaGetSymbolAddress((void**)&psum, g_psum);
    cudaGetSymbolAddress((void**)&src_inv, g_src_inv);
    cudaGetSymbolAddress((void**)&vna_inv, g_vna_inv);
    cudaGetSymbolAddress((void**)&tgt_inv, g_tgt_inv);
    cudaGetSymbolAddress((void**)&lr, g_lr);
    cudaGetSymbolAddress((void**)&semb, g_semb);
    cudaGetSymbolAddress((void**)&Yb, g_Y);
    cudaGetSymbolAddress((void**)&xtb, g_xt);

    cudaFuncSetAttribute(hmma_gemm3m, cudaFuncAttributeMaxDynamicSharedMemorySize, SMEM_GEMM);
    cudaFuncSetAttribute(epi_tgt, cudaFuncAttributeMaxDynamicSharedMemorySize, SMEM_TGT);
    cudaFuncSetAttribute(adp_pass<0>, cudaFuncAttributeMaxDynamicSharedMemorySize, ADPSM);
    cudaFuncSetAttribute(adp_pass<1>, cudaFuncAttributeMaxDynamicSharedMemorySize, ADPSM);

    const size_t SLOT = (size_t)128 * NS;
    u16* Xf3 = Xf + 3 * SLOT;
    const int xS = ((NS + 31) / 32) * 2;   // 314
    const int xT = ((NT + 31) / 32) * 2;   // 250
    const int mhS = 2560, mhT = 2048;
    const size_t psS = (size_t)2 * NS * 128;
    const size_t psT1 = (size_t)2 * NT * 128;
    const size_t psT3 = (size_t)6 * NT * 128;
    const int gS = (NS + 63) / 64, gT = (NT + 63) / 64;   // 79, 63

    // ---- src chain ----
    pack_prep<<<NS / 8, 256>>>(x1, lr, Xf, NS);
    tofp16_kernel<<<(NS * NS / 4 + 255) / 256, 256>>>(A2, A2f, NS * NS / 4);
    nv1_prep<<<(NS * 32 + 255) / 256, 256>>>(src_nv1, nv1h, nv1l, NS);
    nv2_prep<<<(NS + 255) / 256, 256>>>(src_nv2, nv2h, nv2l, NS);
    zero_u<<<(NS + 255) / 256, 256>>>(Mrow, NS);
    adp_pass<0><<<dim3(gS, ADPCS), 256, ADPSM>>>(nv1h, nv1l, nv2h, nv2l, Mrow, (u16*)nullptr, (float*)nullptr, NS, NS);
    adp_pass<1><<<dim3(gS, ADPCS), 256, ADPSM>>>(nv1h, nv1l, nv2h, nv2l, Mrow, Es, psum, NS, NS);
    adp_inv<<<(NS + 255) / 256, 256>>>(psum, src_inv, NS);
    for (int i = 0; i < 2; i++) {
        hmma_gemm3m<<<dim3(xS, 2), 128, SMEM_GEMM>>>(A2f, Es, src_inv,
            Xf + i * SLOT, Yb, NS, NS, mhS, 1);
        epi_src<<<NS / 8, 256>>>(Yb, src_W + i * 8192, src_b + i * 64,
            lr + (size_t)i * NS * 128, lr + (size_t)(i + 1) * NS * 128,
            Xf + (i + 1) * SLOT, NS, psS);
    }

    // ---- rest of prep ----
    pack_prep<<<NT / 8, 256>>>(x0, xtb, Xf3, NT);
    tofp16_kernel<<<(NT * NT / 4 + 255) / 256, 256>>>(A0, A0f, NT * NT / 4);
    tofp16_kernel<<<(NT * NS / 4 + 255) / 256, 256>>>(A1, A1f, NT * NS / 4);
    nv1_prep<<<(NT * 32 + 255) / 256, 256>>>(vna_nv1, nv1h, nv1l, NT);
    nv2_prep<<<(NS + 255) / 256, 256>>>(vna_nv2, nv2h, nv2l, NS);
    zero_u<<<(NT + 255) / 256, 256>>>(Mrow, NT);
    adp_pass<0><<<dim3(gT, ADPCS), 256, ADPSM>>>(nv1h, nv1l, nv2h, nv2l, Mrow, (u16*)nullptr, (float*)nullptr, NT, NS);
    adp_pass<1><<<dim3(gT, ADPCS), 256, ADPSM>>>(nv1h, nv1l, nv2h, nv2l, Mrow, Ev, psum, NT, NS);
    adp_inv<<<(NT + 255) / 256, 256>>>(psum, vna_inv, NT);
    nv1_prep<<<(NT * 32 + 255) / 256, 256>>>(tgt_nv1, nv1h, nv1l, NT);
    nv2_prep<<<(NT + 255) / 256, 256>>>(tgt_nv2, nv2h, nv2l, NT);
    zero_u<<<(NT + 255) / 256, 256>>>(Mrow, NT);
    adp_pass<0><<<dim3(gT, ADPCS), 256, ADPSM>>>(nv1h, nv1l, nv2h, nv2l, Mrow, (u16*)nullptr, (float*)nullptr, NT, NT);
    adp_pass<1><<<dim3(gT, ADPCS), 256, ADPSM>>>(nv1h, nv1l, nv2h, nv2l, Mrow, Et, psum, NT, NT);
    adp_inv<<<(NT + 255) / 256, 256>>>(psum, tgt_inv, NT);

    // ---- VNA block: 3 layers batched, K-split 2 ----
    hmma_gemm3m<<<dim3(xT, 6), 128, SMEM_GEMM>>>(A1f, Ev, vna_inv, Xf, Yb, NT, NS, mhS, 3);
    epi_vna<<<dim3(NT / 8, 3), 256>>>(Yb, vna_W, vna_b, semb, NT, psT3);

    // ---- Target GC block with gated fusion ----
    for (int i = 0; i < 3; i++) {
        hmma_gemm3m<<<dim3(xT, 2), 128, SMEM_GEMM>>>(A0f, Et, tgt_inv, Xf3, Yb, NT, NT, mhT, 1);
        epi_tgt<<<NT / 8, 256, SMEM_TGT>>>(Yb, tgt_W + i * 8192, tgt_b + i * 64,
            semb + (size_t)i * NT * 128, fus_Wt + i * 4096, fus_Ws + i * 4096,
            fus_b + i * 64, xtb, (i < 2) ? Xf3 : (u16*)nullptr, NT, psT1);
    }

    unpack_kernel<<<(NT * 128 + 255) / 256, 256>>>(xtb, (float*)d_out, NT);
}

// round 15
// speedup vs baseline: 1.5522x; 1.0174x over previous
#include <cuda_runtime.h>
#include <cuda_fp16.h>
#include <math.h>
#include <stdint.h>

#define NT 4000
#define NS 5000
#define LOG2E 1.4426950408889634f
typedef unsigned short u16;

// ===================== scratch =============================================
__device__ __align__(16) u16 g_A0f[16000000];
__device__ __align__(16) u16 g_A1f[20000000];
__device__ __align__(16) u16 g_A2f[25000000];
__device__ __align__(16) u16 g_Es[25000000];
__device__ __align__(16) u16 g_Ev[20000000];
__device__ __align__(16) u16 g_Et[16000000];
__device__ __align__(16) u16 g_Xf[2432000];
__device__ __align__(16) u16 g_nv1h[163840], g_nv1l[163840];
__device__ __align__(16) u16 g_nv2h[163840], g_nv2l[163840];
__device__ unsigned g_Mrow[5120];
__device__ float g_psum[40960];
__device__ float g_src_inv[NS];
__device__ float g_vna_inv[NT];
__device__ float g_tgt_inv[NT];
__device__ __align__(16) float g_lr[3 * NS * 128];
__device__ __align__(16) float g_semb[3 * NT * 128];
__device__ __align__(16) float g_Y[6200000];
__device__ __align__(16) float g_xt[NT * 128];

// ===================== PTX helpers =========================================
__device__ __forceinline__ uint32_t smem_u32(const void* p) {
    uint32_t a;
    asm("{ .reg .u64 t; cvta.to.shared.u64 t, %1; cvt.u32.u64 %0, t; }" : "=r"(a) : "l"(p));
    return a;
}
#define CP_ASYNC16(saddr, gaddr, sz) \
    asm volatile("cp.async.ca.shared.global [%0], [%1], 16, %2;" :: "r"(saddr), "l"(gaddr), "r"(sz))
#define CP_COMMIT() asm volatile("cp.async.commit_group;" ::: "memory")
#define CP_WAIT1()  asm volatile("cp.async.wait_group 1;" ::: "memory")
#define CP_WAIT0()  asm volatile("cp.async.wait_group 0;" ::: "memory")
#define LDSM4(r, a) \
    asm volatile("ldmatrix.sync.aligned.m8n8.x4.shared.b16 {%0,%1,%2,%3}, [%4];" \
        : "=r"((r)[0]), "=r"((r)[1]), "=r"((r)[2]), "=r"((r)[3]) : "r"(a))
#define MMA_FP16(c, A, b0, b1) \
    asm volatile("mma.sync.aligned.m16n8k16.row.col.f32.f16.f16.f32 " \
        "{%0,%1,%2,%3},{%4,%5,%6,%7},{%8,%9},{%0,%1,%2,%3};" \
        : "+f"((c)[0]), "+f"((c)[1]), "+f"((c)[2]), "+f"((c)[3]) \
        : "r"((A)[0]), "r"((A)[1]), "r"((A)[2]), "r"((A)[3]), "r"(b0), "r"(b1))

__device__ __forceinline__ uint32_t pack_h2(float a, float b) {
    return (uint32_t)__half_as_ushort(__float2half_rn(a)) |
           ((uint32_t)__half_as_ushort(__float2half_rn(b)) << 16);
}
__device__ __forceinline__ uint4 pack8(const float* v) {
    uint4 H;
    H.x = pack_h2(v[0], v[1]); H.y = pack_h2(v[2], v[3]);
    H.z = pack_h2(v[4], v[5]); H.w = pack_h2(v[6], v[7]);
    return H;
}
__device__ __forceinline__ uint32_t swz(uint32_t x) { return x ^ ((x >> 3) & 0x70); }

// ===================== small kernels ========================================
__global__ void zero_u(unsigned* p, int n) {
    int i = blockIdx.x * blockDim.x + threadIdx.x;
    if (i < n) p[i] = 0u;
}
__global__ void unpack_kernel(const float* __restrict__ xp, float* __restrict__ out, int n) {
    int i = blockIdx.x * blockDim.x + threadIdx.x;
    if (i >= n * 128) return;
    int r = i >> 7, c = i & 127, b = c >> 6, d = c & 63;
    out[((size_t)b * n + r) * 64 + d] = xp[i];
}
__global__ void tofp16_kernel(const float* __restrict__ A, u16* __restrict__ F, int n4) {
    int i = blockIdx.x * blockDim.x + threadIdx.x;
    if (i >= n4) return;
    float4 v = ((const float4*)A)[i];
    uint2 o;
    o.x = pack_h2(v.x * 4096.f, v.y * 4096.f);
    o.y = pack_h2(v.z * 4096.f, v.w * 4096.f);
    ((uint2*)F)[i] = o;
}
__global__ __launch_bounds__(256)
void pack_prep(const float* __restrict__ x, float* __restrict__ xp,
               u16* __restrict__ Xf, int n)
{
    __shared__ float t[8][128];
    const int tid = threadIdx.x, r0 = blockIdx.x * 8;
    for (int i = tid; i < 1024; i += 256) {
        int r = i >> 7, c = i & 127, b = c >> 6, d = c & 63;
        float v = x[((size_t)b * n + r0 + r) * 64 + d];
        xp[(size_t)(r0 + r) * 128 + c] = v;
        t[r][c] = v;
    }
    __syncthreads();
    if (tid < 128) {
        float v[8];
#pragma unroll
        for (int j = 0; j < 8; j++) v[j] = t[j][tid];
        *(uint4*)(Xf + (size_t)tid * n + r0) = pack8(v);
    }
}
__global__ void nv1_prep(const float* __restrict__ nv1, u16* __restrict__ h,
                         u16* __restrict__ l, int n) {
    int i = blockIdx.x * blockDim.x + threadIdx.x;
    if (i >= n * 32) return;
    int r = i >> 5, q = i & 31;
    float v = (q < 30) ? nv1[(size_t)r * 30 + q] : 0.f;
    __half hh = __float2half_rn(v);
    h[i] = __half_as_ushort(hh);
    l[i] = __half_as_ushort(__float2half_rn(v - __half2float(hh)));
}
__global__ void nv2_prep(const float* __restrict__ nv2, u16* __restrict__ h,
                         u16* __restrict__ l, int ncols) {
    int c = blockIdx.x * blockDim.x + threadIdx.x;
    if (c >= ncols) return;
    u16 hb[32], lb[32];
#pragma unroll
    for (int q = 0; q < 32; q++) {
        float v = (q < 30) ? nv2[(size_t)q * ncols + c] : 0.f;
        __half hh = __float2half_rn(v);
        hb[q] = __half_as_ushort(hh);
        lb[q] = __half_as_ushort(__float2half_rn(v - __half2float(hh)));
    }
#pragma unroll
    for (int j = 0; j < 4; j++) {
        ((uint4*)(h + (size_t)c * 32))[j] = ((uint4*)hb)[j];
        ((uint4*)(l + (size_t)c * 32))[j] = ((uint4*)lb)[j];
    }
}

// ===================== adaptive adjacency via tensor cores (R14) ============
#define ADPCS 8
#define ADPSM 49152
template<int MODE>
__global__ __launch_bounds__(256, 2)
void adp_pass(const u16* __restrict__ nv1h, const u16* __restrict__ nv1l,
              const u16* __restrict__ nv2h, const u16* __restrict__ nv2l,
              unsigned* __restrict__ Mrow_g, u16* __restrict__ E,
              float* __restrict__ psum, int nrows, int ncols)
{
    extern __shared__ __align__(128) char dsm[];
    __shared__ float redbuf[2][64];
    __shared__ float MrowS[64];
    const uint32_t sA = smem_u32(dsm), sAl = sA + 8192, sB = sA + 16384, sBl = sA + 32768;
    const int tid = threadIdx.x, lane = tid & 31, wid = tid >> 5;
    const int wm = wid >> 1, wn = wid & 1;
    const int r0 = blockIdx.x * 64, cy = blockIdx.y;

    {
        int r = tid >> 2, cch = tid & 3;
        int gr = r0 + r;
        bool v = gr < nrows;
        size_t gi = (size_t)(v ? gr : 0) * 32 + cch * 8;
        uint32_t sw = swz((uint32_t)r * 128 + cch * 16);
        CP_ASYNC16(sA + sw, nv1h + gi, v ? 16u : 0u);
        if (MODE == 1) CP_ASYNC16(sAl + sw, nv1l + gi, v ? 16u : 0u);
    }
    CP_COMMIT();
    if (MODE == 1 && tid < 64)
        MrowS[tid] = (r0 + tid < nrows) ? __uint_as_float(Mrow_g[r0 + tid]) : 0.f;

    uint32_t arow, axor;
    { int r = wm * 16 + (lane & 7) + (((lane >> 3) & 1) << 3);
      arow = (uint32_t)r * 128; axor = ((uint32_t)r * 16) & 0x70; }
    const uint32_t akbs = ((lane >> 4) & 1) * 16;
    uint32_t brow[4], bxor[4];
#pragma unroll
    for (int bt = 0; bt < 4; bt++) {
        int r = wn * 64 + bt * 16 + (lane & 7) + (((lane >> 4) & 1) << 3);
        brow[bt] = (uint32_t)r * 128; bxor[bt] = ((uint32_t)r * 16) & 0x70;
    }
    const uint32_t bkbs = ((lane >> 3) & 1) * 16;

    const int gr0 = r0 + wm * 16 + (lane >> 2), gr1 = gr0 + 8;
    float mx0 = 0.f, mx1 = 0.f, ps0 = 0.f, ps1 = 0.f;
    float M0 = 0.f, M1 = 0.f;

    const int nch = (ncols + 127) / 128;
    const int cper = (nch + ADPCS - 1) / ADPCS;
    const int chLo = cy * cper, chHi = min(nch, chLo + cper);
    bool mInit = false;
    for (int ch = chLo; ch < chHi; ch++) {
        const int c0 = ch * 128;
        __syncthreads();
#pragma unroll
        for (int t = 0; t < 2; t++) {
            int id = tid + t * 256;
            int j = id >> 2, cch = id & 3;
            int c = c0 + j;
            bool v = c < ncols;
            size_t gi = (size_t)(v ? c : 0) * 32 + cch * 8;
            uint32_t sw = swz((uint32_t)j * 128 + cch * 16);
            CP_ASYNC16(sB + sw, nv2h + gi, v ? 16u : 0u);
            if (MODE == 1) CP_ASYNC16(sBl + sw, nv2l + gi, v ? 16u : 0u);
        }
        CP_COMMIT();
        CP_WAIT0();
        __syncthreads();
        if (MODE == 1 && !mInit) {
            M0 = MrowS[wm * 16 + (lane >> 2)];
            M1 = MrowS[wm * 16 + (lane >> 2) + 8];
            mInit = true;
        }

        float acc[8][4];
#pragma unroll
        for (int j = 0; j < 8; j++)
#pragma unroll
            for (int q = 0; q < 4; q++) acc[j][q] = 0.f;
#pragma unroll
        for (int ks = 0; ks < 2; ks++) {
            const uint32_t kb = ks * 32;
            uint32_t fah[4], fal[4], fbh[4][4], fbl[4][4];
            LDSM4(fah, sA + arow + ((kb + akbs) ^ axor));
            if (MODE == 1) LDSM4(fal, sAl + arow + ((kb + akbs) ^ axor));
#pragma unroll
            for (int bt = 0; bt < 4; bt++) {
                LDSM4(fbh[bt], sB + brow[bt] + ((kb + bkbs) ^ bxor[bt]));
                if (MODE == 1) LDSM4(fbl[bt], sBl + brow[bt] + ((kb + bkbs) ^ bxor[bt]));
            }
#pragma unroll
            for (int nt = 0; nt < 8; nt++) {
                const int g = nt >> 1, h = (nt & 1) << 1;
                MMA_FP16(acc[nt], fah, fbh[g][h], fbh[g][h + 1]);
                if (MODE == 1) {
                    MMA_FP16(acc[nt], fah, fbl[g][h], fbl[g][h + 1]);
                    MMA_FP16(acc[nt], fal, fbh[g][h], fbh[g][h + 1]);
                }
            }
        }

#pragma unroll
        for (int nt = 0; nt < 8; nt++) {
            int c = c0 + wn * 64 + nt * 8 + ((lane & 3) << 1);
            float d00 = fmaxf(acc[nt][0], 0.f), d01 = fmaxf(acc[nt][1], 0.f);
            float d10 = fmaxf(acc[nt][2], 0.f), d11 = fmaxf(acc[nt][3], 0.f);
            if (MODE == 0) {
                if (c < ncols) {
                    mx0 = fmaxf(mx0, fmaxf(d00, d01));
                    mx1 = fmaxf(mx1, fmaxf(d10, d11));
                }
            } else {
                __half2 h0 = __floats2half2_rn((d00 - M0) * LOG2E, (d01 - M0) * LOG2E);
                __half2 h1 = __floats2half2_rn((d10 - M1) * LOG2E, (d11 - M1) * LOG2E);
                uint32_t e0, e1;
                asm("ex2.approx.f16x2 %0, %1;" : "=r"(e0) : "r"(*(uint32_t*)&h0));
                asm("ex2.approx.f16x2 %0, %1;" : "=r"(e1) : "r"(*(uint32_t*)&h1));
                if (c < ncols) {
                    float2 f0 = __half22float2(*(__half2*)&e0);
                    float2 f1 = __half22float2(*(__half2*)&e1);
                    ps0 += f0.x + f0.y;
                    ps1 += f1.x + f1.y;
                    if (gr0 < nrows) *(uint32_t*)(E + (size_t)gr0 * ncols + c) = e0;
                    if (gr1 < nrows) *(uint32_t*)(E + (size_t)gr1 * ncols + c) = e1;
                }
            }
        }
    }

    float v0 = (MODE == 0) ? mx0 : ps0, v1 = (MODE == 0) ? mx1 : ps1;
#pragma unroll
    for (int off = 1; off <= 2; off <<= 1) {
        float o0 = __shfl_xor_sync(0xffffffffu, v0, off);
        float o1 = __shfl_xor_sync(0xffffffffu, v1, off);
        if (MODE == 0) { v0 = fmaxf(v0, o0); v1 = fmaxf(v1, o1); }
        else           { v0 += o0;           v1 += o1; }
    }
    if ((lane & 3) == 0) {
        redbuf[wn][wm * 16 + (lane >> 2)] = v0;
        redbuf[wn][wm * 16 + (lane >> 2) + 8] = v1;
    }
    __syncthreads();
    if (tid < 64 && r0 + tid < nrows) {
        float a = redbuf[0][tid], b = redbuf[1][tid];
        if (MODE == 0)
            atomicMax(Mrow_g + r0 + tid, __float_as_uint(fmaxf(a, b)));
        else
            psum[(size_t)(r0 + tid) * ADPCS + cy] = a + b;
    }
}

__global__ void adp_inv(const float* __restrict__ psum, float* __restrict__ inv, int nrows) {
    int r = blockIdx.x * blockDim.x + threadIdx.x;
    if (r >= nrows) return;
    float s = 0.f;
#pragma unroll
    for (int q = 0; q < ADPCS; q++) s += psum[(size_t)r * ADPCS + q];
    inv[r] = 1.0f / s;
}

// ===================== merged-support split-K GEMM, 32x128 tile =============
// 128 thr, 4 warps (2m x 2n), warp tile 16x64. 16 MMA : 6 LDSM per k-step.
#define GKT 64
#define STG2 24576   // Ad 4K | Ae 4K | B 16K
#define SMEM_GEMM (2 * STG2)

__device__ __forceinline__ void stage_ldm(uint32_t sdst,
    const u16* __restrict__ Ad, const u16* __restrict__ Ae, const u16* __restrict__ B,
    int row0, int kbase, int n, int kend, int m, int tid)
{
#pragma unroll
    for (int t = 0; t < 2; t++) {
        int id = tid + t * 128;
        int r = id >> 3, kc = id & 7;
        int gr = row0 + r, gk = kbase + kc * 8;
        bool v = (gr < n) && (gk < kend);
        size_t gi = (size_t)(v ? gr : 0) * m + (v ? gk : 0);
        uint32_t sw = swz(r * 128 + kc * 16);
        unsigned sz = v ? 16u : 0u;
        CP_ASYNC16(sdst + sw, Ad + gi, sz);
        CP_ASYNC16(sdst + 4096 + sw, Ae + gi, sz);
    }
#pragma unroll
    for (int t = 0; t < 8; t++) {
        int id = tid + t * 128;
        int cr = id >> 3, kc = id & 7;
        int gk = kbase + kc * 8;
        bool v = (gk < kend);
        size_t gi = (size_t)cr * m + (v ? gk : 0);
        uint32_t sw = swz(cr * 128 + kc * 16);
        CP_ASYNC16(sdst + 8192 + sw, B + gi, v ? 16u : 0u);
    }
}

__global__ __launch_bounds__(128, 4)
void hmma_gemm4(const u16* __restrict__ Af, const u16* __restrict__ Ef,
                const float* __restrict__ invsum,
                const u16* __restrict__ Xf,
                float* __restrict__ Y, int n, int m, int mh, int ny)
{
    extern __shared__ __align__(128) char smem[];
    const uint32_t sb = smem_u32(smem);
    const int tid = threadIdx.x, lane = tid & 31, wid = tid >> 5;
    const int wm = wid >> 1, wn = wid & 1;
    const int row0 = blockIdx.x * 32;
    const int yb = blockIdx.y % ny, zs = blockIdx.y / ny;
    const u16* __restrict__ B = Xf + (size_t)yb * 128 * m;
    const int k0 = zs * mh, kend = min(m, k0 + mh);
    const int ktn = (kend - k0 + GKT - 1) / GKT;

    float accD[8][4], accE[8][4];
#pragma unroll
    for (int j = 0; j < 8; j++)
#pragma unroll
        for (int q = 0; q < 4; q++) { accD[j][q] = 0.f; accE[j][q] = 0.f; }

    uint32_t arow, axor;
    { int r = wm * 16 + (lane & 7) + (((lane >> 3) & 1) << 3);
      arow = (uint32_t)r * 128; axor = ((uint32_t)r * 16) & 0x70; }
    const uint32_t akbs = ((lane >> 4) & 1) * 16;
    uint32_t brow[4], bxor[4];
#pragma unroll
    for (int bt = 0; bt < 4; bt++) {
        int r = wn * 64 + bt * 16 + (lane & 7) + (((lane >> 4) & 1) << 3);
        brow[bt] = (uint32_t)r * 128; bxor[bt] = ((uint32_t)r * 16) & 0x70;
    }
    const uint32_t bkbs = ((lane >> 3) & 1) * 16;

    stage_ldm(sb, Af, Ef, B, row0, k0, n, kend, m, tid);
    CP_COMMIT();

    for (int kt = 0; kt < ktn; kt++) {
        if (kt + 1 < ktn)
            stage_ldm(sb + ((kt + 1) & 1) * STG2, Af, Ef, B,
                      row0, k0 + (kt + 1) * GKT, n, kend, m, tid);
        CP_COMMIT();
        CP_WAIT1();
        __syncthreads();
        const uint32_t stb = sb + (kt & 1) * STG2;
#pragma unroll
        for (int ks = 0; ks < 4; ks++) {
            const uint32_t kb = ks * 32;
            uint32_t fad[4], fae[4], fb[4][4];
            LDSM4(fad, stb + arow + ((kb + akbs) ^ axor));
            LDSM4(fae, stb + 4096 + arow + ((kb + akbs) ^ axor));
#pragma unroll
            for (int bt = 0; bt < 4; bt++)
                LDSM4(fb[bt], stb + 8192 + brow[bt] + ((kb + bkbs) ^ bxor[bt]));
#pragma unroll
            for (int nt = 0; nt < 8; nt++) {
                const int g = nt >> 1, h = (nt & 1) << 1;
                MMA_FP16(accD[nt], fad, fb[g][h], fb[g][h + 1]);
                MMA_FP16(accE[nt], fae, fb[g][h], fb[g][h + 1]);
            }
        }
        __syncthreads();
    }

    float* __restrict__ Yd = Y + (size_t)(zs * 2 * ny + yb * 2) * n * 128;
    float* __restrict__ Ye = Yd + (size_t)n * 128;
    const int gr0 = row0 + wm * 16 + (lane >> 2), gr1 = gr0 + 8;
    const float SD = 2.44140625e-4f;
    const float e0 = (gr0 < n) ? invsum[gr0] : 0.f;
    const float e1 = (gr1 < n) ? invsum[gr1] : 0.f;
#pragma unroll
    for (int nt = 0; nt < 8; nt++) {
        int col = wn * 64 + nt * 8 + ((lane & 3) << 1);
        if (gr0 < n) {
            *(float2*)(Yd + (size_t)gr0 * 128 + col) =
                make_float2(accD[nt][0] * SD, accD[nt][1] * SD);
            *(float2*)(Ye + (size_t)gr0 * 128 + col) =
                make_float2(accE[nt][0] * e0, accE[nt][1] * e0);
        }
        if (gr1 < n) {
            *(float2*)(Yd + (size_t)gr1 * 128 + col) =
                make_float2(accD[nt][2] * SD, accD[nt][3] * SD);
            *(float2*)(Ye + (size_t)gr1 * 128 + col) =
                make_float2(accE[nt][2] * e1, accE[nt][3] * e1);
        }
    }
}

// ===================== epilogues (16 rows/CTA, dynamic smem) =================
#define SM_SRC 57344
__global__ __launch_bounds__(256)
void epi_src(const float* __restrict__ Y, const float* __restrict__ W,
             const float* __restrict__ bias, const float* __restrict__ prev,
             float* __restrict__ out, u16* __restrict__ Xf, int n, size_t ps)
{
    extern __shared__ char es[];
    float* Ws = (float*)es;
    float (*Y1s)[128] = (float(*)[128])(es + 32768);
    float (*Y2s)[128] = (float(*)[128])(es + 40960);
    float (*oS)[128]  = (float(*)[128])(es + 49152);
    const int tid = threadIdx.x, r0 = blockIdx.x * 16;
    for (int i = tid; i < 8192; i += 256) Ws[i] = W[i];
    const float* __restrict__ Y2 = Y + (size_t)n * 128;
    for (int i = tid; i < 2048; i += 256) {
        int r = i >> 7, c = i & 127;
        int gr = min(r0 + r, n - 1);
        size_t gi = (size_t)gr * 128 + c;
        Y1s[r][c] = Y[gi] + Y[gi + ps];
        Y2s[r][c] = Y2[gi] + Y2[gi + ps];
    }
    __syncthreads();
    const int c = tid & 127, rg = tid >> 7, d = c & 63, b64 = c & 64;
    const float bv = bias[d];
    for (int rr = rg; rr < 16; rr += 2) {
        int gr = r0 + rr;
        float acc = bv;
#pragma unroll
        for (int k = 0; k < 64; k++) {
            acc = fmaf(Y1s[rr][b64 + k], Ws[k * 64 + d], acc);
            acc = fmaf(Y2s[rr][b64 + k], Ws[(64 + k) * 64 + d], acc);
        }
        float g = 0.f;
        if (gr < n) {
            g = prev[(size_t)gr * 128 + c] + fmaxf(acc, 0.f);
            out[(size_t)gr * 128 + c] = g;
        }
        oS[rr][c] = g;
    }
    __syncthreads();
    if (tid < 128) {
#pragma unroll
        for (int half = 0; half < 2; half++) {
            int rb = r0 + half * 8;
            if (rb < n) {
                float v[8];
#pragma unroll
                for (int j = 0; j < 8; j++) v[j] = oS[half * 8 + j][tid];
                *(uint4*)(Xf + (size_t)tid * n + rb) = pack8(v);
            }
        }
    }
}

#define SM_VNA 49152
__global__ __launch_bounds__(256)
void epi_vna(const float* __restrict__ Y, const float* __restrict__ W,
             const float* __restrict__ bias, float* __restrict__ semb, int n, size_t ps)
{
    extern __shared__ char es[];
    float* Ws = (float*)es;
    float (*Y1s)[128] = (float(*)[128])(es + 32768);
    float (*Y2s)[128] = (float(*)[128])(es + 40960);
    const int tid = threadIdx.x, r0 = blockIdx.x * 16, y = blockIdx.y;
    const float* __restrict__ Wp = W + y * 8192;
    const float* __restrict__ Y1 = Y + (size_t)(2 * y) * n * 128;
    const float* __restrict__ Y2 = Y1 + (size_t)n * 128;
    float* __restrict__ out = semb + (size_t)y * n * 128;
    for (int i = tid; i < 8192; i += 256) Ws[i] = Wp[i];
    for (int i = tid; i < 2048; i += 256) {
        int r = i >> 7, c = i & 127;
        size_t gi = (size_t)(r0 + r) * 128 + c;
        Y1s[r][c] = Y1[gi] + Y1[gi + ps];
        Y2s[r][c] = Y2[gi] + Y2[gi + ps];
    }
    __syncthreads();
    const int c = tid & 127, rg = tid >> 7, d = c & 63, b64 = c & 64;
    const float bv = bias[y * 64 + d];
    for (int rr = rg; rr < 16; rr += 2) {
        float acc = bv;
#pragma unroll
        for (int k = 0; k < 64; k++) {
            acc = fmaf(Y1s[rr][b64 + k], Ws[k * 64 + d], acc);
            acc = fmaf(Y2s[rr][b64 + k], Ws[(64 + k) * 64 + d], acc);
        }
        out[(size_t)(r0 + rr) * 128 + c] = fmaxf(acc, 0.f);
    }
}

#define SM_TGT 65536
__global__ __launch_bounds__(256)
void epi_tgt(const float* __restrict__ Y, const float* __restrict__ W,
             const float* __restrict__ bias, const float* __restrict__ S,
             const float* __restrict__ fWt, const float* __restrict__ fWs,
             const float* __restrict__ fb, float* __restrict__ xt,
             u16* __restrict__ Xf, int n, size_t ps)
{
    extern __shared__ char es[];
    float* Wbuf = (float*)es;
    float (*Y1s)[128] = (float(*)[128])(es + 32768);
    float (*Y2s)[128] = (float(*)[128])(es + 40960);
    float (*tS)[128]  = (float(*)[128])(es + 49152);
    float (*sS)[128]  = (float(*)[128])(es + 57344);
    const int tid = threadIdx.x, r0 = blockIdx.x * 16;
    for (int i = tid; i < 8192; i += 256) Wbuf[i] = W[i];
    const float* __restrict__ Y2 = Y + (size_t)n * 128;
    for (int i = tid; i < 2048; i += 256) {
        int r = i >> 7, c = i & 127;
        size_t gi = (size_t)(r0 + r) * 128 + c;
        Y1s[r][c] = Y[gi] + Y[gi + ps];
        Y2s[r][c] = Y2[gi] + Y2[gi + ps];
        sS[r][c] = S[gi];
    }
    __syncthreads();
    const int c = tid & 127, rg = tid >> 7, d = c & 63, b64 = c & 64;
    const float bv = bias[d];
    for (int rr = rg; rr < 16; rr += 2) {
        float acc = bv;
#pragma unroll
        for (int k = 0; k < 64; k++) {
            acc = fmaf(Y1s[rr][b64 + k], Wbuf[k * 64 + d], acc);
            acc = fmaf(Y2s[rr][b64 + k], Wbuf[(64 + k) * 64 + d], acc);
        }
        tS[rr][c] = fmaxf(acc, 0.f);
    }
    __syncthreads();
    for (int i = tid; i < 4096; i += 256) { Wbuf[i] = fWt[i]; Wbuf[4096 + i] = fWs[i]; }
    __syncthreads();
    const float fbv = fb[d];
    for (int rr = rg; rr < 16; rr += 2) {
        float za = fbv;
#pragma unroll
        for (int k = 0; k < 64; k++) {
            za = fmaf(tS[rr][b64 + k], Wbuf[k * 64 + d], za);
            za = fmaf(sS[rr][b64 + k], Wbuf[4096 + k * 64 + d], za);
        }
        float z = 1.f / (1.f + expf(-za));
        size_t gi = (size_t)(r0 + rr) * 128 + c;
        float nx = xt[gi] + z * tS[rr][c] + (1.f - z) * sS[rr][c];
        xt[gi] = nx;
        Y1s[rr][c] = nx;
    }
    __syncthreads();
    if (Xf && tid < 128) {
#pragma unroll
        for (int half = 0; half < 2; half++) {
            float v[8];
#pragma unroll
            for (int j = 0; j < 8; j++) v[j] = Y1s[half * 8 + j][tid];
            *(uint4*)(Xf + (size_t)tid * n + r0 + half * 8) = pack8(v);
        }
    }
}

// ===================== launcher =============================================
extern "C" void kernel_launch(void* const* d_in, const int* in_sizes, int n_in,
                              void* d_out, int out_size)
{
    (void)in_sizes; (void)n_in; (void)out_size;
    const float* A0      = (const float*)d_in[0];
    const float* A1      = (const float*)d_in[1];
    const float* A2      = (const float*)d_in[2];
    const float* x0      = (const float*)d_in[3];
    const float* x1      = (const float*)d_in[4];
    const float* src_nv1 = (const float*)d_in[5];
    const float* src_nv2 = (const float*)d_in[6];
    const float* src_W   = (const float*)d_in[7];
    const float* src_b   = (const float*)d_in[8];
    const float* vna_nv1 = (const float*)d_in[9];
    const float* vna_nv2 = (const float*)d_in[10];
    const float* vna_W   = (const float*)d_in[11];
    const float* vna_b   = (const float*)d_in[12];
    const float* tgt_nv1 = (const float*)d_in[13];
    const float* tgt_nv2 = (const float*)d_in[14];
    const float* tgt_W   = (const float*)d_in[15];
    const float* tgt_b   = (const float*)d_in[16];
    const float* fus_Wt  = (const float*)d_in[17];
    const float* fus_Ws  = (const float*)d_in[18];
    const float* fus_b   = (const float*)d_in[19];

    u16 *A0f, *A1f, *A2f, *Es, *Ev, *Et, *Xf, *nv1h, *nv1l, *nv2h, *nv2l;
    unsigned* Mrow;
    float *psum, *src_inv, *vna_inv, *tgt_inv, *lr, *semb, *Yb, *xtb;
    cudaGetSymbolAddress((void**)&A0f, g_A0f);
    cudaGetSymbolAddress((void**)&A1f, g_A1f);
    cudaGetSymbolAddress((void**)&A2f, g_A2f);
    cudaGetSymbolAddress((void**)&Es, g_Es);
    cudaGetSymbolAddress((void**)&Ev, g_Ev);
    cudaGetSymbolAddress((void**)&Et, g_Et);
    cudaGetSymbolAddress((void**)&Xf, g_Xf);
    cudaGetSymbolAddress((void**)&nv1h, g_nv1h);
    cudaGetSymbolAddress((void**)&nv1l, g_nv1l);
    cudaGetSymbolAddress((void**)&nv2h, g_nv2h);
    cudaGetSymbolAddress((void**)&nv2l, g_nv2l);
    cudaGetSymbolAddress((void**)&Mrow, g_Mrow);
    cudaGetSymbolAddress((void**)&psum, g_psum);
    cudaGetSymbolAddress((void**)&src_inv, g_src_inv);
    cudaGetSymbolAddress((void**)&vna_inv, g_vna_inv);
    cudaGetSymbolAddress((void**)&tgt_inv, g_tgt_inv);
    cudaGetSymbolAddress((void**)&lr, g_lr);
    cudaGetSymbolAddress((void**)&semb, g_semb);
    cudaGetSymbolAddress((void**)&Yb, g_Y);
    cudaGetSymbolAddress((void**)&xtb, g_xt);

    cudaFuncSetAttribute(hmma_gemm4, cudaFuncAttributeMaxDynamicSharedMemorySize, SMEM_GEMM);
    cudaFuncSetAttribute(epi_src, cudaFuncAttributeMaxDynamicSharedMemorySize, SM_SRC);
    cudaFuncSetAttribute(epi_vna, cudaFuncAttributeMaxDynamicSharedMemorySize, SM_VNA);
    cudaFuncSetAttribute(epi_tgt, cudaFuncAttributeMaxDynamicSharedMemorySize, SM_TGT);
    cudaFuncSetAttribute(adp_pass<0>, cudaFuncAttributeMaxDynamicSharedMemorySize, ADPSM);
    cudaFuncSetAttribute(adp_pass<1>, cudaFuncAttributeMaxDynamicSharedMemorySize, ADPSM);

    const size_t SLOT = (size_t)128 * NS;
    u16* Xf3 = Xf + 3 * SLOT;
    const int xS = (NS + 31) / 32;   // 157
    const int xT = (NT + 31) / 32;   // 125
    const int mhS = 2560, mhT = 2048;
    const size_t psS = (size_t)2 * NS * 128;
    const size_t psT1 = (size_t)2 * NT * 128;
    const size_t psT3 = (size_t)6 * NT * 128;
    const int gS = (NS + 63) / 64, gT = (NT + 63) / 64;

    // ---- src chain ----
    pack_prep<<<NS / 8, 256>>>(x1, lr, Xf, NS);
    tofp16_kernel<<<(NS * NS / 4 + 255) / 256, 256>>>(A2, A2f, NS * NS / 4);
    nv1_prep<<<(NS * 32 + 255) / 256, 256>>>(src_nv1, nv1h, nv1l, NS);
    nv2_prep<<<(NS + 255) / 256, 256>>>(src_nv2, nv2h, nv2l, NS);
    zero_u<<<(NS + 255) / 256, 256>>>(Mrow, NS);
    adp_pass<0><<<dim3(gS, ADPCS), 256, ADPSM>>>(nv1h, nv1l, nv2h, nv2l, Mrow, (u16*)nullptr, (float*)nullptr, NS, NS);
    adp_pass<1><<<dim3(gS, ADPCS), 256, ADPSM>>>(nv1h, nv1l, nv2h, nv2l, Mrow, Es, psum, NS, NS);
    adp_inv<<<(NS + 255) / 256, 256>>>(psum, src_inv, NS);
    for (int i = 0; i < 2; i++) {
        hmma_gemm4<<<dim3(xS, 2), 128, SMEM_GEMM>>>(A2f, Es, src_inv,
            Xf + i * SLOT, Yb, NS, NS, mhS, 1);
        epi_src<<<(NS + 15) / 16, 256, SM_SRC>>>(Yb, src_W + i * 8192, src_b + i * 64,
            lr + (size_t)i * NS * 128, lr + (size_t)(i + 1) * NS * 128,
            Xf + (i + 1) * SLOT, NS, psS);
    }

    // ---- rest of prep ----
    pack_prep<<<NT / 8, 256>>>(x0, xtb, Xf3, NT);
    tofp16_kernel<<<(NT * NT / 4 + 255) / 256, 256>>>(A0, A0f, NT * NT / 4);
    tofp16_kernel<<<(NT * NS / 4 + 255) / 256, 256>>>(A1, A1f, NT * NS / 4);
    nv1_prep<<<(NT * 32 + 255) / 256, 256>>>(vna_nv1, nv1h, nv1l, NT);
    nv2_prep<<<(NS + 255) / 256, 256>>>(vna_nv2, nv2h, nv2l, NS);
    zero_u<<<(NT + 255) / 256, 256>>>(Mrow, NT);
    adp_pass<0><<<dim3(gT, ADPCS), 256, ADPSM>>>(nv1h, nv1l, nv2h, nv2l, Mrow, (u16*)nullptr, (float*)nullptr, NT, NS);
    adp_pass<1><<<dim3(gT, ADPCS), 256, ADPSM>>>(nv1h, nv1l, nv2h, nv2l, Mrow, Ev, psum, NT, NS);
    adp_inv<<<(NT + 255) / 256, 256>>>(psum, vna_inv, NT);
    nv1_prep<<<(NT * 32 + 255) / 256, 256>>>(tgt_nv1, nv1h, nv1l, NT);
    nv2_prep<<<(NT + 255) / 256, 256>>>(tgt_nv2, nv2h, nv2l, NT);
    zero_u<<<(NT + 255) / 256, 256>>>(Mrow, NT);
    adp_pass<0><<<dim3(gT, ADPCS), 256, ADPSM>>>(nv1h, nv1l, nv2h, nv2l, Mrow, (u16*)nullptr, (float*)nullptr, NT, NT);
    adp_pass<1><<<dim3(gT, ADPCS), 256, ADPSM>>>(nv1h, nv1l, nv2h, nv2l, Mrow, Et, psum, NT, NT);
    adp_inv<<<(NT + 255) / 256, 256>>>(psum, tgt_inv, NT);

    // ---- VNA block: 3 layers batched, K-split 2 ----
    hmma_gemm4<<<dim3(xT, 6), 128, SMEM_GEMM>>>(A1f, Ev, vna_inv, Xf, Yb, NT, NS, mhS, 3);
    epi_vna<<<dim3(NT / 16, 3), 256, SM_VNA>>>(Yb, vna_W, vna_b, semb, NT, psT3);

    // ---- Target GC block with gated fusion ----
    for (int i = 0; i < 3; i++) {
        hmma_gemm4<<<dim3(xT, 2), 128, SMEM_GEMM>>>(A0f, Et, tgt_inv, Xf3, Yb, NT, NT, mhT, 1);
        epi_tgt<<<NT / 16, 256, SM_TGT>>>(Yb, tgt_W + i * 8192, tgt_b + i * 64,
            semb + (size_t)i * NT * 128, fus_Wt + i * 4096, fus_Ws + i * 4096,
            fus_b + i * 64, xtb, (i < 2) ? Xf3 : (u16*)nullptr, NT, psT1);
    }

    unpack_kernel<<<(NT * 128 + 255) / 256, 256>>>(xtb, (float*)d_out, NT);
}

// round 16
// speedup vs baseline: 1.6593x; 1.0690x over previous
#include <cuda_runtime.h>
#include <cuda_fp16.h>
#include <math.h>
#include <stdint.h>

#define NT 4000
#define NS 5000
#define LOG2E 1.4426950408889634f
typedef unsigned short u16;

// ===================== scratch =============================================
__device__ __align__(16) u16 g_A0f[16000000];
__device__ __align__(16) u16 g_A1f[20000000];
__device__ __align__(16) u16 g_A2f[25000000];
__device__ __align__(16) u16 g_Es[25000000];
__device__ __align__(16) u16 g_Ev[20000000];
__device__ __align__(16) u16 g_Et[16000000];
__device__ __align__(16) u16 g_Xf[2432000];
__device__ __align__(16) u16 g_nv1h[3][163840], g_nv1l[3][163840];
__device__ __align__(16) u16 g_nv2h[3][163840], g_nv2l[3][163840];
__device__ unsigned g_Mrow[3][5120];
__device__ float g_psum[3][40960];
__device__ float g_src_inv[NS];
__device__ float g_vna_inv[NT];
__device__ float g_tgt_inv[NT];
__device__ __align__(16) float g_lr[3 * NS * 128];
__device__ __align__(16) float g_semb[3 * NT * 128];
__device__ __align__(16) float g_Y[6200000];
__device__ __align__(16) float g_xt[NT * 128];

// ===================== PTX helpers =========================================
__device__ __forceinline__ uint32_t smem_u32(const void* p) {
    uint32_t a;
    asm("{ .reg .u64 t; cvta.to.shared.u64 t, %1; cvt.u32.u64 %0, t; }" : "=r"(a) : "l"(p));
    return a;
}
#define CP_ASYNC16(saddr, gaddr, sz) \
    asm volatile("cp.async.ca.shared.global [%0], [%1], 16, %2;" :: "r"(saddr), "l"(gaddr), "r"(sz))
#define CP_COMMIT() asm volatile("cp.async.commit_group;" ::: "memory")
#define CP_WAIT1()  asm volatile("cp.async.wait_group 1;" ::: "memory")
#define CP_WAIT0()  asm volatile("cp.async.wait_group 0;" ::: "memory")
#define LDSM4(r, a) \
    asm volatile("ldmatrix.sync.aligned.m8n8.x4.shared.b16 {%0,%1,%2,%3}, [%4];" \
        : "=r"((r)[0]), "=r"((r)[1]), "=r"((r)[2]), "=r"((r)[3]) : "r"(a))
#define MMA_FP16(c, A, b0, b1) \
    asm volatile("mma.sync.aligned.m16n8k16.row.col.f32.f16.f16.f32 " \
        "{%0,%1,%2,%3},{%4,%5,%6,%7},{%8,%9},{%0,%1,%2,%3};" \
        : "+f"((c)[0]), "+f"((c)[1]), "+f"((c)[2]), "+f"((c)[3]) \
        : "r"((A)[0]), "r"((A)[1]), "r"((A)[2]), "r"((A)[3]), "r"(b0), "r"(b1))

__device__ __forceinline__ uint32_t pack_h2(float a, float b) {
    return (uint32_t)__half_as_ushort(__float2half_rn(a)) |
           ((uint32_t)__half_as_ushort(__float2half_rn(b)) << 16);
}
__device__ __forceinline__ uint4 pack8(const float* v) {
    uint4 H;
    H.x = pack_h2(v[0], v[1]); H.y = pack_h2(v[2], v[3]);
    H.z = pack_h2(v[4], v[5]); H.w = pack_h2(v[6], v[7]);
    return H;
}
__device__ __forceinline__ uint32_t swz(uint32_t x) { return x ^ ((x >> 3) & 0x70); }

// ===================== small kernels ========================================
__global__ void zero_u(unsigned* p, int n) {
    int i = blockIdx.x * blockDim.x + threadIdx.x;
    if (i < n) p[i] = 0u;
}
__global__ void unpack_kernel(const float* __restrict__ xp, float* __restrict__ out, int n) {
    int i = blockIdx.x * blockDim.x + threadIdx.x;
    if (i >= n * 128) return;
    int r = i >> 7, c = i & 127, b = c >> 6, d = c & 63;
    out[((size_t)b * n + r) * 64 + d] = xp[i];
}
__global__ void tofp16_kernel(const float* __restrict__ A, u16* __restrict__ F, int n4) {
    int i = blockIdx.x * blockDim.x + threadIdx.x;
    if (i >= n4) return;
    float4 v = ((const float4*)A)[i];
    uint2 o;
    o.x = pack_h2(v.x * 4096.f, v.y * 4096.f);
    o.y = pack_h2(v.z * 4096.f, v.w * 4096.f);
    ((uint2*)F)[i] = o;
}
__global__ __launch_bounds__(256)
void pack_prep(const float* __restrict__ x, float* __restrict__ xp,
               u16* __restrict__ Xf, int n)
{
    __shared__ float t[8][128];
    const int tid = threadIdx.x, r0 = blockIdx.x * 8;
    for (int i = tid; i < 1024; i += 256) {
        int r = i >> 7, c = i & 127, b = c >> 6, d = c & 63;
        float v = x[((size_t)b * n + r0 + r) * 64 + d];
        xp[(size_t)(r0 + r) * 128 + c] = v;
        t[r][c] = v;
    }
    __syncthreads();
    if (tid < 128) {
        float v[8];
#pragma unroll
        for (int j = 0; j < 8; j++) v[j] = t[j][tid];
        *(uint4*)(Xf + (size_t)tid * n + r0) = pack8(v);
    }
}
__global__ void nv1_prep(const float* __restrict__ nv1, u16* __restrict__ h,
                         u16* __restrict__ l, int n) {
    int i = blockIdx.x * blockDim.x + threadIdx.x;
    if (i >= n * 32) return;
    int r = i >> 5, q = i & 31;
    float v = (q < 30) ? nv1[(size_t)r * 30 + q] : 0.f;
    __half hh = __float2half_rn(v);
    h[i] = __half_as_ushort(hh);
    l[i] = __half_as_ushort(__float2half_rn(v - __half2float(hh)));
}
__global__ void nv2_prep(const float* __restrict__ nv2, u16* __restrict__ h,
                         u16* __restrict__ l, int ncols) {
    int c = blockIdx.x * blockDim.x + threadIdx.x;
    if (c >= ncols) return;
    u16 hb[32], lb[32];
#pragma unroll
    for (int q = 0; q < 32; q++) {
        float v = (q < 30) ? nv2[(size_t)q * ncols + c] : 0.f;
        __half hh = __float2half_rn(v);
        hb[q] = __half_as_ushort(hh);
        lb[q] = __half_as_ushort(__float2half_rn(v - __half2float(hh)));
    }
#pragma unroll
    for (int j = 0; j < 4; j++) {
        ((uint4*)(h + (size_t)c * 32))[j] = ((uint4*)hb)[j];
        ((uint4*)(l + (size_t)c * 32))[j] = ((uint4*)lb)[j];
    }
}

// ===================== adaptive adjacency via tensor cores ==================
#define ADPCS 8
#define ADPSM 49152
template<int MODE>
__global__ __launch_bounds__(256, 2)
void adp_pass(const u16* __restrict__ nv1h, const u16* __restrict__ nv1l,
              const u16* __restrict__ nv2h, const u16* __restrict__ nv2l,
              unsigned* __restrict__ Mrow_g, u16* __restrict__ E,
              float* __restrict__ psum, int nrows, int ncols)
{
    extern __shared__ __align__(128) char dsm[];
    __shared__ float redbuf[2][64];
    __shared__ float MrowS[64];
    const uint32_t sA = smem_u32(dsm), sAl = sA + 8192, sB = sA + 16384, sBl = sA + 32768;
    const int tid = threadIdx.x, lane = tid & 31, wid = tid >> 5;
    const int wm = wid >> 1, wn = wid & 1;
    const int r0 = blockIdx.x * 64, cy = blockIdx.y;

    {
        int r = tid >> 2, cch = tid & 3;
        int gr = r0 + r;
        bool v = gr < nrows;
        size_t gi = (size_t)(v ? gr : 0) * 32 + cch * 8;
        uint32_t sw = swz((uint32_t)r * 128 + cch * 16);
        CP_ASYNC16(sA + sw, nv1h + gi, v ? 16u : 0u);
        if (MODE == 1) CP_ASYNC16(sAl + sw, nv1l + gi, v ? 16u : 0u);
    }
    CP_COMMIT();
    if (MODE == 1 && tid < 64)
        MrowS[tid] = (r0 + tid < nrows) ? __uint_as_float(Mrow_g[r0 + tid]) : 0.f;

    uint32_t arow, axor;
    { int r = wm * 16 + (lane & 7) + (((lane >> 3) & 1) << 3);
      arow = (uint32_t)r * 128; axor = ((uint32_t)r * 16) & 0x70; }
    const uint32_t akbs = ((lane >> 4) & 1) * 16;
    uint32_t brow[4], bxor[4];
#pragma unroll
    for (int bt = 0; bt < 4; bt++) {
        int r = wn * 64 + bt * 16 + (lane & 7) + (((lane >> 4) & 1) << 3);
        brow[bt] = (uint32_t)r * 128; bxor[bt] = ((uint32_t)r * 16) & 0x70;
    }
    const uint32_t bkbs = ((lane >> 3) & 1) * 16;

    const int gr0 = r0 + wm * 16 + (lane >> 2), gr1 = gr0 + 8;
    float mx0 = 0.f, mx1 = 0.f, ps0 = 0.f, ps1 = 0.f;
    float M0 = 0.f, M1 = 0.f;

    const int nch = (ncols + 127) / 128;
    const int cper = (nch + ADPCS - 1) / ADPCS;
    const int chLo = cy * cper, chHi = min(nch, chLo + cper);
    bool mInit = false;
    for (int ch = chLo; ch < chHi; ch++) {
        const int c0 = ch * 128;
        __syncthreads();
#pragma unroll
        for (int t = 0; t < 2; t++) {
            int id = tid + t * 256;
            int j = id >> 2, cch = id & 3;
            int c = c0 + j;
            bool v = c < ncols;
            size_t gi = (size_t)(v ? c : 0) * 32 + cch * 8;
            uint32_t sw = swz((uint32_t)j * 128 + cch * 16);
            CP_ASYNC16(sB + sw, nv2h + gi, v ? 16u : 0u);
            if (MODE == 1) CP_ASYNC16(sBl + sw, nv2l + gi, v ? 16u : 0u);
        }
        CP_COMMIT();
        CP_WAIT0();
        __syncthreads();
        if (MODE == 1 && !mInit) {
            M0 = MrowS[wm * 16 + (lane >> 2)];
            M1 = MrowS[wm * 16 + (lane >> 2) + 8];
            mInit = true;
        }

        float acc[8][4];
#pragma unroll
        for (int j = 0; j < 8; j++)
#pragma unroll
            for (int q = 0; q < 4; q++) acc[j][q] = 0.f;
#pragma unroll
        for (int ks = 0; ks < 2; ks++) {
            const uint32_t kb = ks * 32;
            uint32_t fah[4], fal[4], fbh[4][4], fbl[4][4];
            LDSM4(fah, sA + arow + ((kb + akbs) ^ axor));
            if (MODE == 1) LDSM4(fal, sAl + arow + ((kb + akbs) ^ axor));
#pragma unroll
            for (int bt = 0; bt < 4; bt++) {
                LDSM4(fbh[bt], sB + brow[bt] + ((kb + bkbs) ^ bxor[bt]));
                if (MODE == 1) LDSM4(fbl[bt], sBl + brow[bt] + ((kb + bkbs) ^ bxor[bt]));
            }
#pragma unroll
            for (int nt = 0; nt < 8; nt++) {
                const int g = nt >> 1, h = (nt & 1) << 1;
                MMA_FP16(acc[nt], fah, fbh[g][h], fbh[g][h + 1]);
                if (MODE == 1) {
                    MMA_FP16(acc[nt], fah, fbl[g][h], fbl[g][h + 1]);
                    MMA_FP16(acc[nt], fal, fbh[g][h], fbh[g][h + 1]);
                }
            }
        }

#pragma unroll
        for (int nt = 0; nt < 8; nt++) {
            int c = c0 + wn * 64 + nt * 8 + ((lane & 3) << 1);
            float d00 = fmaxf(acc[nt][0], 0.f), d01 = fmaxf(acc[nt][1], 0.f);
            float d10 = fmaxf(acc[nt][2], 0.f), d11 = fmaxf(acc[nt][3], 0.f);
            if (MODE == 0) {
                if (c < ncols) {
                    mx0 = fmaxf(mx0, fmaxf(d00, d01));
                    mx1 = fmaxf(mx1, fmaxf(d10, d11));
                }
            } else {
                __half2 h0 = __floats2half2_rn((d00 - M0) * LOG2E, (d01 - M0) * LOG2E);
                __half2 h1 = __floats2half2_rn((d10 - M1) * LOG2E, (d11 - M1) * LOG2E);
                uint32_t e0, e1;
                asm("ex2.approx.f16x2 %0, %1;" : "=r"(e0) : "r"(*(uint32_t*)&h0));
                asm("ex2.approx.f16x2 %0, %1;" : "=r"(e1) : "r"(*(uint32_t*)&h1));
                if (c < ncols) {
                    float2 f0 = __half22float2(*(__half2*)&e0);
                    float2 f1 = __half22float2(*(__half2*)&e1);
                    ps0 += f0.x + f0.y;
                    ps1 += f1.x + f1.y;
                    if (gr0 < nrows) *(uint32_t*)(E + (size_t)gr0 * ncols + c) = e0;
                    if (gr1 < nrows) *(uint32_t*)(E + (size_t)gr1 * ncols + c) = e1;
                }
            }
        }
    }

    float v0 = (MODE == 0) ? mx0 : ps0, v1 = (MODE == 0) ? mx1 : ps1;
#pragma unroll
    for (int off = 1; off <= 2; off <<= 1) {
        float o0 = __shfl_xor_sync(0xffffffffu, v0, off);
        float o1 = __shfl_xor_sync(0xffffffffu, v1, off);
        if (MODE == 0) { v0 = fmaxf(v0, o0); v1 = fmaxf(v1, o1); }
        else           { v0 += o0;           v1 += o1; }
    }
    if ((lane & 3) == 0) {
        redbuf[wn][wm * 16 + (lane >> 2)] = v0;
        redbuf[wn][wm * 16 + (lane >> 2) + 8] = v1;
    }
    __syncthreads();
    if (tid < 64 && r0 + tid < nrows) {
        float a = redbuf[0][tid], b = redbuf[1][tid];
        if (MODE == 0)
            atomicMax(Mrow_g + r0 + tid, __float_as_uint(fmaxf(a, b)));
        else
            psum[(size_t)(r0 + tid) * ADPCS + cy] = a + b;
    }
}

__global__ void adp_inv(const float* __restrict__ psum, float* __restrict__ inv, int nrows) {
    int r = blockIdx.x * blockDim.x + threadIdx.x;
    if (r >= nrows) return;
    float s = 0.f;
#pragma unroll
    for (int q = 0; q < ADPCS; q++) s += psum[(size_t)r * ADPCS + q];
    inv[r] = 1.0f / s;
}

// ===================== merged-support split-K GEMM, 32x128 tile =============
#define GKT 64
#define STG2 24576
#define SMEM_GEMM (2 * STG2)

__device__ __forceinline__ void stage_ldm(uint32_t sdst,
    const u16* __restrict__ Ad, const u16* __restrict__ Ae, const u16* __restrict__ B,
    int row0, int kbase, int n, int kend, int m, int tid)
{
#pragma unroll
    for (int t = 0; t < 2; t++) {
        int id = tid + t * 128;
        int r = id >> 3, kc = id & 7;
        int gr = row0 + r, gk = kbase + kc * 8;
        bool v = (gr < n) && (gk < kend);
        size_t gi = (size_t)(v ? gr : 0) * m + (v ? gk : 0);
        uint32_t sw = swz(r * 128 + kc * 16);
        unsigned sz = v ? 16u : 0u;
        CP_ASYNC16(sdst + sw, Ad + gi, sz);
        CP_ASYNC16(sdst + 4096 + sw, Ae + gi, sz);
    }
#pragma unroll
    for (int t = 0; t < 8; t++) {
        int id = tid + t * 128;
        int cr = id >> 3, kc = id & 7;
        int gk = kbase + kc * 8;
        bool v = (gk < kend);
        size_t gi = (size_t)cr * m + (v ? gk : 0);
        uint32_t sw = swz(cr * 128 + kc * 16);
        CP_ASYNC16(sdst + 8192 + sw, B + gi, v ? 16u : 0u);
    }
}

__global__ __launch_bounds__(128, 4)
void hmma_gemm4(const u16* __restrict__ Af, const u16* __restrict__ Ef,
                const float* __restrict__ invsum,
                const u16* __restrict__ Xf,
                float* __restrict__ Y, int n, int m, int mh, int ny)
{
    extern __shared__ __align__(128) char smem[];
    const uint32_t sb = smem_u32(smem);
    const int tid = threadIdx.x, lane = tid & 31, wid = tid >> 5;
    const int wm = wid >> 1, wn = wid & 1;
    const int row0 = blockIdx.x * 32;
    const int yb = blockIdx.y % ny, zs = blockIdx.y / ny;
    const u16* __restrict__ B = Xf + (size_t)yb * 128 * m;
    const int k0 = zs * mh, kend = min(m, k0 + mh);
    const int ktn = (kend - k0 + GKT - 1) / GKT;

    float accD[8][4], accE[8][4];
#pragma unroll
    for (int j = 0; j < 8; j++)
#pragma unroll
        for (int q = 0; q < 4; q++) { accD[j][q] = 0.f; accE[j][q] = 0.f; }

    uint32_t arow, axor;
    { int r = wm * 16 + (lane & 7) + (((lane >> 3) & 1) << 3);
      arow = (uint32_t)r * 128; axor = ((uint32_t)r * 16) & 0x70; }
    const uint32_t akbs = ((lane >> 4) & 1) * 16;
    uint32_t brow[4], bxor[4];
#pragma unroll
    for (int bt = 0; bt < 4; bt++) {
        int r = wn * 64 + bt * 16 + (lane & 7) + (((lane >> 4) & 1) << 3);
        brow[bt] = (uint32_t)r * 128; bxor[bt] = ((uint32_t)r * 16) & 0x70;
    }
    const uint32_t bkbs = ((lane >> 3) & 1) * 16;

    stage_ldm(sb, Af, Ef, B, row0, k0, n, kend, m, tid);
    CP_COMMIT();

    for (int kt = 0; kt < ktn; kt++) {
        if (kt + 1 < ktn)
            stage_ldm(sb + ((kt + 1) & 1) * STG2, Af, Ef, B,
                      row0, k0 + (kt + 1) * GKT, n, kend, m, tid);
        CP_COMMIT();
        CP_WAIT1();
        __syncthreads();
        const uint32_t stb = sb + (kt & 1) * STG2;
#pragma unroll
        for (int ks = 0; ks < 4; ks++) {
            const uint32_t kb = ks * 32;
            uint32_t fad[4], fae[4], fb[4][4];
            LDSM4(fad, stb + arow + ((kb + akbs) ^ axor));
            LDSM4(fae, stb + 4096 + arow + ((kb + akbs) ^ axor));
#pragma unroll
            for (int bt = 0; bt < 4; bt++)
                LDSM4(fb[bt], stb + 8192 + brow[bt] + ((kb + bkbs) ^ bxor[bt]));
#pragma unroll
            for (int nt = 0; nt < 8; nt++) {
                const int g = nt >> 1, h = (nt & 1) << 1;
                MMA_FP16(accD[nt], fad, fb[g][h], fb[g][h + 1]);
                MMA_FP16(accE[nt], fae, fb[g][h], fb[g][h + 1]);
            }
        }
        __syncthreads();
    }

    float* __restrict__ Yd = Y + (size_t)(zs * 2 * ny + yb * 2) * n * 128;
    float* __restrict__ Ye = Yd + (size_t)n * 128;
    const int gr0 = row0 + wm * 16 + (lane >> 2), gr1 = gr0 + 8;
    const float SD = 2.44140625e-4f;
    const float e0 = (gr0 < n) ? invsum[gr0] : 0.f;
    const float e1 = (gr1 < n) ? invsum[gr1] : 0.f;
#pragma unroll
    for (int nt = 0; nt < 8; nt++) {
        int col = wn * 64 + nt * 8 + ((lane & 3) << 1);
        if (gr0 < n) {
            *(float2*)(Yd + (size_t)gr0 * 128 + col) =
                make_float2(accD[nt][0] * SD, accD[nt][1] * SD);
            *(float2*)(Ye + (size_t)gr0 * 128 + col) =
                make_float2(accE[nt][0] * e0, accE[nt][1] * e0);
        }
        if (gr1 < n) {
            *(float2*)(Yd + (size_t)gr1 * 128 + col) =
                make_float2(accD[nt][2] * SD, accD[nt][3] * SD);
            *(float2*)(Ye + (size_t)gr1 * 128 + col) =
                make_float2(accE[nt][2] * e1, accE[nt][3] * e1);
        }
    }
}

// ===================== epilogues (16 rows/CTA, dynamic smem) =================
#define SM_SRC 57344
__global__ __launch_bounds__(256)
void epi_src(const float* __restrict__ Y, const float* __restrict__ W,
             const float* __restrict__ bias, const float* __restrict__ prev,
             float* __restrict__ out, u16* __restrict__ Xf, int n, size_t ps)
{
    extern __shared__ char es[];
    float* Ws = (float*)es;
    float (*Y1s)[128] = (float(*)[128])(es + 32768);
    float (*Y2s)[128] = (float(*)[128])(es + 40960);
    float (*oS)[128]  = (float(*)[128])(es + 49152);
    const int tid = threadIdx.x, r0 = blockIdx.x * 16;
    for (int i = tid; i < 8192; i += 256) Ws[i] = W[i];
    const float* __restrict__ Y2 = Y + (size_t)n * 128;
    for (int i = tid; i < 2048; i += 256) {
        int r = i >> 7, c = i & 127;
        int gr = min(r0 + r, n - 1);
        size_t gi = (size_t)gr * 128 + c;
        Y1s[r][c] = Y[gi] + Y[gi + ps];
        Y2s[r][c] = Y2[gi] + Y2[gi + ps];
    }
    __syncthreads();
    const int c = tid & 127, rg = tid >> 7, d = c & 63, b64 = c & 64;
    const float bv = bias[d];
    for (int rr = rg; rr < 16; rr += 2) {
        int gr = r0 + rr;
        float acc = bv;
#pragma unroll
        for (int k = 0; k < 64; k++) {
            acc = fmaf(Y1s[rr][b64 + k], Ws[k * 64 + d], acc);
            acc = fmaf(Y2s[rr][b64 + k], Ws[(64 + k) * 64 + d], acc);
        }
        float g = 0.f;
        if (gr < n) {
            g = prev[(size_t)gr * 128 + c] + fmaxf(acc, 0.f);
            out[(size_t)gr * 128 + c] = g;
        }
        oS[rr][c] = g;
    }
    __syncthreads();
    if (tid < 128) {
#pragma unroll
        for (int half = 0; half < 2; half++) {
            int rb = r0 + half * 8;
            if (rb < n) {
                float v[8];
#pragma unroll
                for (int j = 0; j < 8; j++) v[j] = oS[half * 8 + j][tid];
                *(uint4*)(Xf + (size_t)tid * n + rb) = pack8(v);
            }
        }
    }
}

#define SM_VNA 49152
__global__ __launch_bounds__(256)
void epi_vna(const float* __restrict__ Y, const float* __restrict__ W,
             const float* __restrict__ bias, float* __restrict__ semb, int n, size_t ps)
{
    extern __shared__ char es[];
    float* Ws = (float*)es;
    float (*Y1s)[128] = (float(*)[128])(es + 32768);
    float (*Y2s)[128] = (float(*)[128])(es + 40960);
    const int tid = threadIdx.x, r0 = blockIdx.x * 16, y = blockIdx.y;
    const float* __restrict__ Wp = W + y * 8192;
    const float* __restrict__ Y1 = Y + (size_t)(2 * y) * n * 128;
    const float* __restrict__ Y2 = Y1 + (size_t)n * 128;
    float* __restrict__ out = semb + (size_t)y * n * 128;
    for (int i = tid; i < 8192; i += 256) Ws[i] = Wp[i];
    for (int i = tid; i < 2048; i += 256) {
        int r = i >> 7, c = i & 127;
        size_t gi = (size_t)(r0 + r) * 128 + c;
        Y1s[r][c] = Y1[gi] + Y1[gi + ps];
        Y2s[r][c] = Y2[gi] + Y2[gi + ps];
    }
    __syncthreads();
    const int c = tid & 127, rg = tid >> 7, d = c & 63, b64 = c & 64;
    const float bv = bias[y * 64 + d];
    for (int rr = rg; rr < 16; rr += 2) {
        float acc = bv;
#pragma unroll
        for (int k = 0; k < 64; k++) {
            acc = fmaf(Y1s[rr][b64 + k], Ws[k * 64 + d], acc);
            acc = fmaf(Y2s[rr][b64 + k], Ws[(64 + k) * 64 + d], acc);
        }
        out[(size_t)(r0 + rr) * 128 + c] = fmaxf(acc, 0.f);
    }
}

#define SM_TGT 65536
__global__ __launch_bounds__(256)
void epi_tgt(const float* __restrict__ Y, const float* __restrict__ W,
             const float* __restrict__ bias, const float* __restrict__ S,
             const float* __restrict__ fWt, const float* __restrict__ fWs,
             const float* __restrict__ fb, float* __restrict__ xt,
             u16* __restrict__ Xf, int n, size_t ps)
{
    extern __shared__ char es[];
    float* Wbuf = (float*)es;
    float (*Y1s)[128] = (float(*)[128])(es + 32768);
    float (*Y2s)[128] = (float(*)[128])(es + 40960);
    float (*tS)[128]  = (float(*)[128])(es + 49152);
    float (*sS)[128]  = (float(*)[128])(es + 57344);
    const int tid = threadIdx.x, r0 = blockIdx.x * 16;
    for (int i = tid; i < 8192; i += 256) Wbuf[i] = W[i];
    const float* __restrict__ Y2 = Y + (size_t)n * 128;
    for (int i = tid; i < 2048; i += 256) {
        int r = i >> 7, c = i & 127;
        size_t gi = (size_t)(r0 + r) * 128 + c;
        Y1s[r][c] = Y[gi] + Y[gi + ps];
        Y2s[r][c] = Y2[gi] + Y2[gi + ps];
        sS[r][c] = S[gi];
    }
    __syncthreads();
    const int c = tid & 127, rg = tid >> 7, d = c & 63, b64 = c & 64;
    const float bv = bias[d];
    for (int rr = rg; rr < 16; rr += 2) {
        float acc = bv;
#pragma unroll
        for (int k = 0; k < 64; k++) {
            acc = fmaf(Y1s[rr][b64 + k], Wbuf[k * 64 + d], acc);
            acc = fmaf(Y2s[rr][b64 + k], Wbuf[(64 + k) * 64 + d], acc);
        }
        tS[rr][c] = fmaxf(acc, 0.f);
    }
    __syncthreads();
    for (int i = tid; i < 4096; i += 256) { Wbuf[i] = fWt[i]; Wbuf[4096 + i] = fWs[i]; }
    __syncthreads();
    const float fbv = fb[d];
    for (int rr = rg; rr < 16; rr += 2) {
        float za = fbv;
#pragma unroll
        for (int k = 0; k < 64; k++) {
            za = fmaf(tS[rr][b64 + k], Wbuf[k * 64 + d], za);
            za = fmaf(sS[rr][b64 + k], Wbuf[4096 + k * 64 + d], za);
        }
        float z = 1.f / (1.f + expf(-za));
        size_t gi = (size_t)(r0 + rr) * 128 + c;
        float nx = xt[gi] + z * tS[rr][c] + (1.f - z) * sS[rr][c];
        xt[gi] = nx;
        Y1s[rr][c] = nx;
    }
    __syncthreads();
    if (Xf && tid < 128) {
#pragma unroll
        for (int half = 0; half < 2; half++) {
            float v[8];
#pragma unroll
            for (int j = 0; j < 8; j++) v[j] = Y1s[half * 8 + j][tid];
            *(uint4*)(Xf + (size_t)tid * n + r0 + half * 8) = pack8(v);
        }
    }
}

// ===================== launcher =============================================
extern "C" void kernel_launch(void* const* d_in, const int* in_sizes, int n_in,
                              void* d_out, int out_size)
{
    (void)in_sizes; (void)n_in; (void)out_size;
    const float* A0      = (const float*)d_in[0];
    const float* A1      = (const float*)d_in[1];
    const float* A2      = (const float*)d_in[2];
    const float* x0      = (const float*)d_in[3];
    const float* x1      = (const float*)d_in[4];
    const float* src_nv1 = (const float*)d_in[5];
    const float* src_nv2 = (const float*)d_in[6];
    const float* src_W   = (const float*)d_in[7];
    const float* src_b   = (const float*)d_in[8];
    const float* vna_nv1 = (const float*)d_in[9];
    const float* vna_nv2 = (const float*)d_in[10];
    const float* vna_W   = (const float*)d_in[11];
    const float* vna_b   = (const float*)d_in[12];
    const float* tgt_nv1 = (const float*)d_in[13];
    const float* tgt_nv2 = (const float*)d_in[14];
    const float* tgt_W   = (const float*)d_in[15];
    const float* tgt_b   = (const float*)d_in[16];
    const float* fus_Wt  = (const float*)d_in[17];
    const float* fus_Ws  = (const float*)d_in[18];
    const float* fus_b   = (const float*)d_in[19];

    u16 *A0f, *A1f, *A2f, *Es, *Ev, *Et, *Xf;
    u16 *nv1hB, *nv1lB, *nv2hB, *nv2lB;
    unsigned* MrowB;
    float *psumB, *src_inv, *vna_inv, *tgt_inv, *lr, *semb, *Yb, *xtb;
    cudaGetSymbolAddress((void**)&A0f, g_A0f);
    cudaGetSymbolAddress((void**)&A1f, g_A1f);
    cudaGetSymbolAddress((void**)&A2f, g_A2f);
    cudaGetSymbolAddress((void**)&Es, g_Es);
    cudaGetSymbolAddress((void**)&Ev, g_Ev);
    cudaGetSymbolAddress((void**)&Et, g_Et);
    cudaGetSymbolAddress((void**)&Xf, g_Xf);
    cudaGetSymbolAddress((void**)&nv1hB, g_nv1h);
    cudaGetSymbolAddress((void**)&nv1lB, g_nv1l);
    cudaGetSymbolAddress((void**)&nv2hB, g_nv2h);
    cudaGetSymbolAddress((void**)&nv2lB, g_nv2l);
    cudaGetSymbolAddress((void**)&MrowB, g_Mrow);
    cudaGetSymbolAddress((void**)&psumB, g_psum);
    cudaGetSymbolAddress((void**)&src_inv, g_src_inv);
    cudaGetSymbolAddress((void**)&vna_inv, g_vna_inv);
    cudaGetSymbolAddress((void**)&tgt_inv, g_tgt_inv);
    cudaGetSymbolAddress((void**)&lr, g_lr);
    cudaGetSymbolAddress((void**)&semb, g_semb);
    cudaGetSymbolAddress((void**)&Yb, g_Y);
    cudaGetSymbolAddress((void**)&xtb, g_xt);

    cudaFuncSetAttribute(hmma_gemm4, cudaFuncAttributeMaxDynamicSharedMemorySize, SMEM_GEMM);
    cudaFuncSetAttribute(epi_src, cudaFuncAttributeMaxDynamicSharedMemorySize, SM_SRC);
    cudaFuncSetAttribute(epi_vna, cudaFuncAttributeMaxDynamicSharedMemorySize, SM_VNA);
    cudaFuncSetAttribute(epi_tgt, cudaFuncAttributeMaxDynamicSharedMemorySize, SM_TGT);
    cudaFuncSetAttribute(adp_pass<0>, cudaFuncAttributeMaxDynamicSharedMemorySize, ADPSM);
    cudaFuncSetAttribute(adp_pass<1>, cudaFuncAttributeMaxDynamicSharedMemorySize, ADPSM);

    // one-time stream/event creation (no device memory involved)
    static cudaStream_t s2 = nullptr;
    static cudaEvent_t evF = nullptr, evJ = nullptr;
    if (!s2) {
        cudaStreamCreateWithFlags(&s2, cudaStreamNonBlocking);
        cudaEventCreateWithFlags(&evF, cudaEventDisableTiming);
        cudaEventCreateWithFlags(&evJ, cudaEventDisableTiming);
    }

    const size_t SLOT = (size_t)128 * NS;
    u16* Xf3 = Xf + 3 * SLOT;
    const int xS = (NS + 31) / 32;   // 157
    const int xT = (NT + 31) / 32;   // 125
    const int mhS = 2560, mhT = 2048;
    const size_t psS = (size_t)2 * NS * 128;
    const size_t psT1 = (size_t)2 * NT * 128;
    const size_t psT3 = (size_t)6 * NT * 128;
    const int gS = (NS + 63) / 64, gT = (NT + 63) / 64;

    // per-adjacency buffer sets (0=src on main stream, 1=vna, 2=tgt on s2)
    u16 *n1h0 = nv1hB, *n1l0 = nv1lB, *n2h0 = nv2hB, *n2l0 = nv2lB;
    u16 *n1h1 = nv1hB + 163840, *n1l1 = nv1lB + 163840, *n2h1 = nv2hB + 163840, *n2l1 = nv2lB + 163840;
    u16 *n1h2 = nv1hB + 327680, *n1l2 = nv1lB + 327680, *n2h2 = nv2hB + 327680, *n2l2 = nv2lB + 327680;
    unsigned *Mr0 = MrowB, *Mr1 = MrowB + 5120, *Mr2 = MrowB + 10240;
    float *ps0 = psumB, *ps1 = psumB + 40960, *ps2 = psumB + 81920;

    // -------- fork --------
    cudaEventRecord(evF, 0);
    cudaStreamWaitEvent(s2, evF, 0);

    // -------- s2: independent prep chain --------
    pack_prep<<<NT / 8, 256, 0, s2>>>(x0, xtb, Xf3, NT);
    tofp16_kernel<<<(NT * NT / 4 + 255) / 256, 256, 0, s2>>>(A0, A0f, NT * NT / 4);
    tofp16_kernel<<<(NT * NS / 4 + 255) / 256, 256, 0, s2>>>(A1, A1f, NT * NS / 4);
    nv1_prep<<<(NT * 32 + 255) / 256, 256, 0, s2>>>(vna_nv1, n1h1, n1l1, NT);
    nv2_prep<<<(NS + 255) / 256, 256, 0, s2>>>(vna_nv2, n2h1, n2l1, NS);
    zero_u<<<(NT + 255) / 256, 256, 0, s2>>>(Mr1, NT);
    adp_pass<0><<<dim3(gT, ADPCS), 256, ADPSM, s2>>>(n1h1, n1l1, n2h1, n2l1, Mr1, (u16*)nullptr, (float*)nullptr, NT, NS);
    adp_pass<1><<<dim3(gT, ADPCS), 256, ADPSM, s2>>>(n1h1, n1l1, n2h1, n2l1, Mr1, Ev, ps1, NT, NS);
    adp_inv<<<(NT + 255) / 256, 256, 0, s2>>>(ps1, vna_inv, NT);
    nv1_prep<<<(NT * 32 + 255) / 256, 256, 0, s2>>>(tgt_nv1, n1h2, n1l2, NT);
    nv2_prep<<<(NT + 255) / 256, 256, 0, s2>>>(tgt_nv2, n2h2, n2l2, NT);
    zero_u<<<(NT + 255) / 256, 256, 0, s2>>>(Mr2, NT);
    adp_pass<0><<<dim3(gT, ADPCS), 256, ADPSM, s2>>>(n1h2, n1l2, n2h2, n2l2, Mr2, (u16*)nullptr, (float*)nullptr, NT, NT);
    adp_pass<1><<<dim3(gT, ADPCS), 256, ADPSM, s2>>>(n1h2, n1l2, n2h2, n2l2, Mr2, Et, ps2, NT, NT);
    adp_inv<<<(NT + 255) / 256, 256, 0, s2>>>(ps2, tgt_inv, NT);
    cudaEventRecord(evJ, s2);

    // -------- main stream: src chain --------
    pack_prep<<<NS / 8, 256>>>(x1, lr, Xf, NS);
    tofp16_kernel<<<(NS * NS / 4 + 255) / 256, 256>>>(A2, A2f, NS * NS / 4);
    nv1_prep<<<(NS * 32 + 255) / 256, 256>>>(src_nv1, n1h0, n1l0, NS);
    nv2_prep<<<(NS + 255) / 256, 256>>>(src_nv2, n2h0, n2l0, NS);
    zero_u<<<(NS + 255) / 256, 256>>>(Mr0, NS);
    adp_pass<0><<<dim3(gS, ADPCS), 256, ADPSM>>>(n1h0, n1l0, n2h0, n2l0, Mr0, (u16*)nullptr, (float*)nullptr, NS, NS);
    adp_pass<1><<<dim3(gS, ADPCS), 256, ADPSM>>>(n1h0, n1l0, n2h0, n2l0, Mr0, Es, ps0, NS, NS);
    adp_inv<<<(NS + 255) / 256, 256>>>(ps0, src_inv, NS);
    for (int i = 0; i < 2; i++) {
        hmma_gemm4<<<dim3(xS, 2), 128, SMEM_GEMM>>>(A2f, Es, src_inv,
            Xf + i * SLOT, Yb, NS, NS, mhS, 1);
        epi_src<<<(NS + 15) / 16, 256, SM_SRC>>>(Yb, src_W + i * 8192, src_b + i * 64,
            lr + (size_t)i * NS * 128, lr + (size_t)(i + 1) * NS * 128,
            Xf + (i + 1) * SLOT, NS, psS);
    }

    // -------- join --------
    cudaStreamWaitEvent(0, evJ, 0);

    // ---- VNA block: 3 layers batched, K-split 2 ----
    hmma_gemm4<<<dim3(xT, 6), 128, SMEM_GEMM>>>(A1f, Ev, vna_inv, Xf, Yb, NT, NS, mhS, 3);
    epi_vna<<<dim3(NT / 16, 3), 256, SM_VNA>>>(Yb, vna_W, vna_b, semb, NT, psT3);

    // ---- Target GC block with gated fusion ----
    for (int i = 0; i < 3; i++) {
        hmma_gemm4<<<dim3(xT, 2), 128, SMEM_GEMM>>>(A0f, Et, tgt_inv, Xf3, Yb, NT, NT, mhT, 1);
        epi_tgt<<<NT / 16, 256, SM_TGT>>>(Yb, tgt_W + i * 8192, tgt_b + i * 64,
            semb + (size_t)i * NT * 128, fus_Wt + i * 4096, fus_Ws + i * 4096,
            fus_b + i * 64, xtb, (i < 2) ? Xf3 : (u16*)nullptr, NT, psT1);
    }

    unpack_kernel<<<(NT * 128 + 255) / 256, 256>>>(xtb, (float*)d_out, NT);
}